// round 13
// baseline (speedup 1.0000x reference)
#include <cuda_runtime.h>
#include <cuda_fp16.h>
#include <cuda_bf16.h>
#include <cstdint>

#define NNODES 100000
#define NEDGES 300000
#define GDIM   2048
#define HIDDIM 256
#define EDIM   64
#define NLAYER 3
#define NBLK   ((NNODES + 255) / 256)   // 391
#define NCHUNK 4
#define NPC    ((NNODES + NCHUNK - 1) / NCHUNK)   // 25000 nodes per chunk

// ---------------- static device scratch ----------------
__device__ __half g_x16[(size_t)NNODES * HIDDIM];
__device__ __half g_buf16A[(size_t)NNODES * HIDDIM];
__device__ __half g_buf16B[(size_t)NNODES * HIDDIM];
__device__ __half g_xl[(size_t)NNODES * HIDDIM];
__device__ __half g_xr[(size_t)NNODES * HIDDIM];
__device__ __half g_eproj[(size_t)NEDGES * HIDDIM];     // CSR-sorted order
__device__ __half g_ea16[(size_t)NEDGES * EDIM];        // edge_attr fp16, CSR order
__device__ __half g_wlt[(size_t)NLAYER * HIDDIM * HIDDIM];
__device__ __half g_wrt[(size_t)NLAYER * HIDDIM * HIDDIM];
__device__ __half g_wet[(size_t)NLAYER * HIDDIM * EDIM];
__device__ float g_eloop[NLAYER * HIDDIM];
__device__ float g_esum[EDIM];
// CSR (dst-sorted edges)
__device__ int g_cnt[NNODES];
__device__ int g_bsum[512];
__device__ int g_rowptr[NNODES + 1];
__device__ int g_woff[NNODES];
__device__ int g_ssrc[NEDGES];
__device__ int g_seid[NEDGES];
__device__ int g_gstart[GDIM + 1];

// ---------------- helpers ----------------
__device__ __forceinline__ void mma_f16(float* c, const uint32_t* a, const uint32_t* b) {
    asm volatile("mma.sync.aligned.m16n8k16.row.col.f32.f16.f16.f32 "
                 "{%0,%1,%2,%3}, {%4,%5,%6,%7}, {%8,%9}, {%0,%1,%2,%3};"
                 : "+f"(c[0]), "+f"(c[1]), "+f"(c[2]), "+f"(c[3])
                 : "r"(a[0]), "r"(a[1]), "r"(a[2]), "r"(a[3]), "r"(b[0]), "r"(b[1]));
}
__device__ __forceinline__ void cp16(void* smem, const void* gmem) {
    uint32_t s;
    asm("{ .reg .u64 t; cvta.to.shared.u64 t, %1; cvt.u32.u64 %0, t; }" : "=r"(s) : "l"(smem));
    asm volatile("cp.async.cg.shared.global [%0], [%1], 16;" :: "r"(s), "l"(gmem));
}
__device__ __forceinline__ int swz(int row, int col) {
    return ((((col >> 3) ^ ((row >> 1) & 3)) << 3) | (col & 7));
}
__device__ __forceinline__ uint4 pack8h(float4 a, float4 b) {
    uint4 u;
    *(__half2*)&u.x = __floats2half2_rn(a.x, a.y);
    *(__half2*)&u.y = __floats2half2_rn(a.z, a.w);
    *(__half2*)&u.z = __floats2half2_rn(b.x, b.y);
    *(__half2*)&u.w = __floats2half2_rn(b.z, b.w);
    return u;
}
__device__ __forceinline__ void fp16x8_expand(uint4 u, float4& o0, float4& o1) {
    float2 f0 = __half22float2(*(__half2*)&u.x);
    float2 f1 = __half22float2(*(__half2*)&u.y);
    float2 f2 = __half22float2(*(__half2*)&u.z);
    float2 f3 = __half22float2(*(__half2*)&u.w);
    o0 = make_float4(f0.x, f0.y, f1.x, f1.y);
    o1 = make_float4(f2.x, f2.y, f3.x, f3.y);
}

// ========== fp16 GEMM: cp.async 2-stage, BK=32, CTA 128x128, 8 warps 4x2 ==========
#define GEMM_LOAD16(s, k0, Ap, Bp, K, M, row0, col0)                                  \
    _Pragma("unroll") for (int i = 0; i < 2; i++) {                                   \
        int idx = tid + i * 256;                                                      \
        int r = idx >> 2, q = (idx & 3) * 8;                                          \
        int ar = (row0) + r; if (ar >= (M)) ar = (M) - 1;                             \
        cp16(&As[s][r][swz(r, q)], (Ap) + (size_t)ar * (K) + (k0) + q);               \
        cp16(&Bs[s][r][swz(r, q)], (Bp) + (size_t)((col0) + r) * (K) + (k0) + q);     \
    }                                                                                 \
    asm volatile("cp.async.commit_group;" ::: "memory");

#define GEMM_BODY16(Ap, Bp, K, M, row0, col0)                                          \
    float acc[2][8][4];                                                               \
    _Pragma("unroll") for (int mt = 0; mt < 2; mt++)                                  \
    _Pragma("unroll") for (int nt = 0; nt < 8; nt++)                                  \
    _Pragma("unroll") for (int i = 0; i < 4; i++) acc[mt][nt][i] = 0.0f;              \
    GEMM_LOAD16(0, 0, Ap, Bp, K, M, row0, col0)                                       \
    const int NKC = (K) / 32;                                                         \
    for (int kc = 0; kc < NKC; kc++) {                                                \
        if (kc + 1 < NKC) {                                                           \
            GEMM_LOAD16((kc + 1) & 1, (kc + 1) * 32, Ap, Bp, K, M, row0, col0)        \
            asm volatile("cp.async.wait_group 1;" ::: "memory");                      \
        } else {                                                                      \
            asm volatile("cp.async.wait_group 0;" ::: "memory");                      \
        }                                                                             \
        __syncthreads();                                                              \
        const int st = kc & 1;                                                        \
        _Pragma("unroll") for (int ks = 0; ks < 2; ks++) {                            \
            const int kb = ks * 16;                                                   \
            uint32_t bf[8][2];                                                        \
            _Pragma("unroll") for (int nt = 0; nt < 8; nt++) {                        \
                const int bn = warp_n * 64 + nt * 8 + lq;                             \
                bf[nt][0] = *(const uint32_t*)&Bs[st][bn][swz(bn, kb + lr * 2)];      \
                bf[nt][1] = *(const uint32_t*)&Bs[st][bn][swz(bn, kb + lr * 2 + 8)];  \
            }                                                                         \
            _Pragma("unroll") for (int mt = 0; mt < 2; mt++) {                        \
                const int ar = warp_m * 32 + mt * 16 + lq;                            \
                uint32_t af[4];                                                       \
                af[0] = *(const uint32_t*)&As[st][ar][swz(ar, kb + lr * 2)];          \
                af[1] = *(const uint32_t*)&As[st][ar + 8][swz(ar + 8, kb + lr * 2)];  \
                af[2] = *(const uint32_t*)&As[st][ar][swz(ar, kb + lr * 2 + 8)];      \
                af[3] = *(const uint32_t*)&As[st][ar + 8][swz(ar + 8, kb + lr * 2 + 8)]; \
                _Pragma("unroll") for (int nt = 0; nt < 8; nt++)                      \
                    mma_f16(acc[mt][nt], af, bf[nt]);                                 \
            }                                                                         \
        }                                                                             \
        __syncthreads();                                                              \
    }

// ---------------- fused node GEMM ----------------
__global__ __launch_bounds__(256)
void gemm_node(const __half* __restrict__ A,
               const __half* __restrict__ Wlt, const __half* __restrict__ Wrt,
               const float* __restrict__ bl_, const float* __restrict__ br_,
               __half* __restrict__ Cl, __half* __restrict__ Cr, int M) {
    __shared__ __align__(16) __half As[2][128][32];
    __shared__ __align__(16) __half Bs[2][128][32];
    const int tid = threadIdx.x, warp = tid >> 5, lane = tid & 31;
    const int warp_m = warp & 3, warp_n = warp >> 2;
    const int row0 = blockIdx.x * 128;
    const int col0 = (blockIdx.y & 1) * 128;
    const __half* W   = (blockIdx.y < 2) ? Wlt : Wrt;
    const float* bias = (blockIdx.y < 2) ? bl_ : br_;
    __half* C         = (blockIdx.y < 2) ? Cl  : Cr;
    const int lq = lane >> 2, lr = lane & 3;

    GEMM_BODY16(A, W, 256, M, row0, col0)

    const int r_base = row0 + warp_m * 32 + lq;
    const int c_base = col0 + warp_n * 64 + lr * 2;
#pragma unroll
    for (int nt = 0; nt < 8; nt++) {
        int c = c_base + nt * 8;
        float2 bv = *(const float2*)(bias + c);
#pragma unroll
        for (int mt = 0; mt < 2; mt++) {
            int r = r_base + mt * 16;
            if (r < M) {
                __half2 v = __floats2half2_rn(acc[mt][nt][0] + bv.x, acc[mt][nt][1] + bv.y);
                *(__half2*)(C + (size_t)r * 256 + c) = v;
            }
            if (r + 8 < M) {
                __half2 v = __floats2half2_rn(acc[mt][nt][2] + bv.x, acc[mt][nt][3] + bv.y);
                *(__half2*)(C + (size_t)(r + 8) * 256 + c) = v;
            }
        }
    }
}

// ---------------- edge GEMM (chunked): only rows in [rowptr[nlo], rowptr[nhi]) ----------------
__global__ __launch_bounds__(256)
void gemm_edge(const __half* __restrict__ Wet, int nlo, int nhi) {
    const int row0 = blockIdx.x * 128;
    const int r_lo = g_rowptr[nlo], r_hi = g_rowptr[nhi];
    if (row0 + 128 <= r_lo || row0 >= r_hi) return;   // outside this chunk

    __shared__ __align__(16) __half As[2][128][32];
    __shared__ __align__(16) __half Bs[2][128][32];
    const __half* A = g_ea16;
    const int tid = threadIdx.x, warp = tid >> 5, lane = tid & 31;
    const int warp_m = warp & 3, warp_n = warp >> 2;
    const int col0 = blockIdx.y * 128;
    const int lq = lane >> 2, lr = lane & 3;
    const int M = NEDGES;

    GEMM_BODY16(A, Wet, 64, M, row0, col0)

    const int r_base = row0 + warp_m * 32 + lq;
    const int c_base = col0 + warp_n * 64 + lr * 2;
#pragma unroll
    for (int nt = 0; nt < 8; nt++) {
        int c = c_base + nt * 8;
#pragma unroll
        for (int mt = 0; mt < 2; mt++) {
            int r = r_base + mt * 16;
            if (r < M) {
                __half2 v = __floats2half2_rn(acc[mt][nt][0], acc[mt][nt][1]);
                *(__half2*)(g_eproj + (size_t)r * 256 + c) = v;
            }
            if (r + 8 < M) {
                __half2 v = __floats2half2_rn(acc[mt][nt][2], acc[mt][nt][3]);
                *(__half2*)(g_eproj + (size_t)(r + 8) * 256 + c) = v;
            }
        }
    }
}

// ---------------- conversion kernels ----------------
__global__ void convx_kernel(const float* __restrict__ x) {
    int i = blockIdx.x * blockDim.x + threadIdx.x;
    if (i >= NNODES * 32) return;
    const float4* s = (const float4*)x + (size_t)i * 2;
    ((uint4*)g_x16)[i] = pack8h(s[0], s[1]);
}
__global__ void convw_kernel(const float* __restrict__ W, __half* __restrict__ Wt, int K) {
    __shared__ float t[32][33];
    int l = blockIdx.z;
    const float* Wl = W + (size_t)l * K * 256;
    __half* Wtl = Wt + (size_t)l * K * 256;
    int n0 = blockIdx.x * 32, k0 = blockIdx.y * 32;
    int tx = threadIdx.x, ty = threadIdx.y;
#pragma unroll
    for (int j = 0; j < 32; j += 8) t[ty + j][tx] = Wl[(size_t)(k0 + ty + j) * 256 + n0 + tx];
    __syncthreads();
#pragma unroll
    for (int j = 0; j < 32; j += 8)
        Wtl[(size_t)(n0 + ty + j) * K + k0 + tx] = __float2half(t[tx][ty + j]);
}

// ---------------- CSR build ----------------
__global__ void hist_kernel(const int* __restrict__ dst) {
    int e = blockIdx.x * blockDim.x + threadIdx.x;
    if (e < NEDGES) atomicAdd(&g_cnt[dst[e]], 1);
}
__global__ void blocksum_kernel() {
    int i = blockIdx.x * 256 + threadIdx.x;
    int v = (i < NNODES) ? g_cnt[i] : 0;
    __shared__ int ws[8];
#pragma unroll
    for (int o = 16; o; o >>= 1) v += __shfl_down_sync(0xffffffffu, v, o);
    if ((threadIdx.x & 31) == 0) ws[threadIdx.x >> 5] = v;
    __syncthreads();
    if (threadIdx.x == 0) {
        int s = 0;
#pragma unroll
        for (int j = 0; j < 8; j++) s += ws[j];
        g_bsum[blockIdx.x] = s;
    }
}
__global__ void scanb_kernel() {
    __shared__ int sm[512];
    int i = threadIdx.x;
    int v = (i < NBLK) ? g_bsum[i] : 0;
    sm[i] = v;
    __syncthreads();
    for (int s = 1; s < 512; s <<= 1) {
        int t = (i >= s) ? sm[i - s] : 0;
        __syncthreads();
        sm[i] += t;
        __syncthreads();
    }
    if (i < NBLK) g_bsum[i] = sm[i] - v;
}
__global__ void rowptr_kernel() {
    int tid = threadIdx.x;
    int i = blockIdx.x * 256 + tid;
    int v = (i < NNODES) ? g_cnt[i] : 0;
    __shared__ int sm[256];
    sm[tid] = v;
    __syncthreads();
    for (int s = 1; s < 256; s <<= 1) {
        int t = (tid >= s) ? sm[tid - s] : 0;
        __syncthreads();
        sm[tid] += t;
        __syncthreads();
    }
    int ex = sm[tid] - v + g_bsum[blockIdx.x];
    if (i < NNODES) { g_rowptr[i] = ex; g_woff[i] = ex; }
    if (i == NNODES - 1) g_rowptr[NNODES] = NEDGES;
}
__global__ void fill_kernel(const int* __restrict__ src, const int* __restrict__ dst) {
    int e = blockIdx.x * blockDim.x + threadIdx.x;
    if (e >= NEDGES) return;
    int d = dst[e];
    int pos = atomicAdd(&g_woff[d], 1);
    g_ssrc[pos] = src[e];
    g_seid[pos] = e;
}
__global__ void permute_ea_kernel(const float* __restrict__ ea) {
    int gt = blockIdx.x * blockDim.x + threadIdx.x;
    if (gt >= NEDGES * 8) return;
    int i = gt >> 3, q = gt & 7;
    int e = g_seid[i];
    const float4* s = (const float4*)(ea + (size_t)e * 64 + q * 8);
    ((uint4*)g_ea16)[(size_t)i * 8 + q] = pack8h(s[0], s[1]);
}
__global__ void gbounds_kernel(const int* __restrict__ batch) {
    int g = blockIdx.x * blockDim.x + threadIdx.x;
    if (g > GDIM) return;
    int lo = 0, hi = NNODES;
    while (lo < hi) {
        int mid = (lo + hi) >> 1;
        if (batch[mid] < g) lo = mid + 1; else hi = mid;
    }
    g_gstart[g] = lo;
}

// ---------------- edge_attr column sums + eloop ----------------
__global__ void esum_kernel(const float* __restrict__ ea) {
    int col = threadIdx.x & 63;
    int rowsPerBlk = blockDim.x >> 6;
    int r0 = blockIdx.x * rowsPerBlk + (threadIdx.x >> 6);
    int rstride = gridDim.x * rowsPerBlk;
    float s = 0.0f;
    for (int r = r0; r < NEDGES; r += rstride) s += ea[(size_t)r * EDIM + col];
    atomicAdd(&g_esum[col], s);
}
__global__ void eloop_kernel(const float* __restrict__ We) {
    int l = blockIdx.x;
    int j = threadIdx.x;
    const float* W = We + (size_t)l * EDIM * 256;
    const float inv = 1.0f / (float)NEDGES;
    float acc = 0.0f;
#pragma unroll
    for (int k = 0; k < EDIM; k++) acc = fmaf(g_esum[k] * inv, W[k * 256 + j], acc);
    g_eloop[l * 256 + j] = acc;
}

// ---------------- fused GAT edge phase (chunked over dst nodes) ----------------
__global__ __launch_bounds__(256)
void fused_gat_kernel(const float* __restrict__ att, const float* __restrict__ bias,
                      const float* __restrict__ eloop, __half* __restrict__ xn,
                      int nbase, int nend) {
    int gt = blockIdx.x * blockDim.x + threadIdx.x;
    int d = nbase + (gt >> 5), lane = gt & 31;
    if (d >= nend) return;
    const int off = lane * 8;

    float4 xr0, xr1;
    fp16x8_expand(*(const uint4*)(g_xr + (size_t)d * 256 + off), xr0, xr1);
    float4 at0 = *(const float4*)(att + off);
    float4 at1 = *(const float4*)(att + off + 4);

    float acc[8];
    float denom;
    {
        float4 a0, a1;
        fp16x8_expand(*(const uint4*)(g_xl + (size_t)d * 256 + off), a0, a1);
        float4 e0 = *(const float4*)(eloop + off);
        float4 e1 = *(const float4*)(eloop + off + 4);
        float t = 0.0f, m;
        m = a0.x + xr0.x + e0.x; m = fmaxf(m, 0.2f * m); t = fmaf(m, at0.x, t);
        m = a0.y + xr0.y + e0.y; m = fmaxf(m, 0.2f * m); t = fmaf(m, at0.y, t);
        m = a0.z + xr0.z + e0.z; m = fmaxf(m, 0.2f * m); t = fmaf(m, at0.z, t);
        m = a0.w + xr0.w + e0.w; m = fmaxf(m, 0.2f * m); t = fmaf(m, at0.w, t);
        m = a1.x + xr1.x + e1.x; m = fmaxf(m, 0.2f * m); t = fmaf(m, at1.x, t);
        m = a1.y + xr1.y + e1.y; m = fmaxf(m, 0.2f * m); t = fmaf(m, at1.y, t);
        m = a1.z + xr1.z + e1.z; m = fmaxf(m, 0.2f * m); t = fmaf(m, at1.z, t);
        m = a1.w + xr1.w + e1.w; m = fmaxf(m, 0.2f * m); t = fmaf(m, at1.w, t);
        t += __shfl_down_sync(0xffffffffu, t, 4, 8);
        t += __shfl_down_sync(0xffffffffu, t, 2, 8);
        t += __shfl_down_sync(0xffffffffu, t, 1, 8);
        float p = __expf(__shfl_sync(0xffffffffu, t, 0, 8));
        denom = p;
        acc[0] = p * a0.x; acc[1] = p * a0.y; acc[2] = p * a0.z; acc[3] = p * a0.w;
        acc[4] = p * a1.x; acc[5] = p * a1.y; acc[6] = p * a1.z; acc[7] = p * a1.w;
    }
    const int beg = g_rowptr[d], end = g_rowptr[d + 1];
    uint4 au, eu;
    if (beg < end) {
        int s = g_ssrc[beg];
        au = *(const uint4*)(g_xl + (size_t)s * 256 + off);
        eu = *(const uint4*)(g_eproj + (size_t)beg * 256 + off);
    }
    for (int i = beg; i < end; i++) {
        uint4 a_cur = au, e_cur = eu;
        if (i + 1 < end) {
            int s = g_ssrc[i + 1];
            au = *(const uint4*)(g_xl + (size_t)s * 256 + off);
            eu = *(const uint4*)(g_eproj + (size_t)(i + 1) * 256 + off);
        }
        float4 a0, a1, e0, e1;
        fp16x8_expand(a_cur, a0, a1);
        fp16x8_expand(e_cur, e0, e1);
        float t = 0.0f, m;
        m = a0.x + xr0.x + e0.x; m = fmaxf(m, 0.2f * m); t = fmaf(m, at0.x, t);
        m = a0.y + xr0.y + e0.y; m = fmaxf(m, 0.2f * m); t = fmaf(m, at0.y, t);
        m = a0.z + xr0.z + e0.z; m = fmaxf(m, 0.2f * m); t = fmaf(m, at0.z, t);
        m = a0.w + xr0.w + e0.w; m = fmaxf(m, 0.2f * m); t = fmaf(m, at0.w, t);
        m = a1.x + xr1.x + e1.x; m = fmaxf(m, 0.2f * m); t = fmaf(m, at1.x, t);
        m = a1.y + xr1.y + e1.y; m = fmaxf(m, 0.2f * m); t = fmaf(m, at1.y, t);
        m = a1.z + xr1.z + e1.z; m = fmaxf(m, 0.2f * m); t = fmaf(m, at1.z, t);
        m = a1.w + xr1.w + e1.w; m = fmaxf(m, 0.2f * m); t = fmaf(m, at1.w, t);
        t += __shfl_down_sync(0xffffffffu, t, 4, 8);
        t += __shfl_down_sync(0xffffffffu, t, 2, 8);
        t += __shfl_down_sync(0xffffffffu, t, 1, 8);
        float p = __expf(__shfl_sync(0xffffffffu, t, 0, 8));
        denom += p;
        acc[0] = fmaf(p, a0.x, acc[0]); acc[1] = fmaf(p, a0.y, acc[1]);
        acc[2] = fmaf(p, a0.z, acc[2]); acc[3] = fmaf(p, a0.w, acc[3]);
        acc[4] = fmaf(p, a1.x, acc[4]); acc[5] = fmaf(p, a1.y, acc[5]);
        acc[6] = fmaf(p, a1.z, acc[6]); acc[7] = fmaf(p, a1.w, acc[7]);
    }
    float inv = 1.0f / (denom + 1e-16f);
    float4 b0 = *(const float4*)(bias + off);
    float4 b1 = *(const float4*)(bias + off + 4);
    float4 o0, o1;
    o0.x = fmaxf(fmaf(acc[0], inv, b0.x), 0.f); o0.y = fmaxf(fmaf(acc[1], inv, b0.y), 0.f);
    o0.z = fmaxf(fmaf(acc[2], inv, b0.z), 0.f); o0.w = fmaxf(fmaf(acc[3], inv, b0.w), 0.f);
    o1.x = fmaxf(fmaf(acc[4], inv, b1.x), 0.f); o1.y = fmaxf(fmaf(acc[5], inv, b1.y), 0.f);
    o1.z = fmaxf(fmaf(acc[6], inv, b1.z), 0.f); o1.w = fmaxf(fmaf(acc[7], inv, b1.w), 0.f);
    *(uint4*)(xn + (size_t)d * 256 + off) = pack8h(o0, o1);
}

// ---------------- fused pool + MLP: one block per graph (batch is sorted) ----------------
__global__ __launch_bounds__(256)
void poolmlp_kernel(const __half* __restrict__ xf,
                    const float* __restrict__ Wp1, const float* __restrict__ bp1,
                    const float* __restrict__ Wp2, const float* __restrict__ bp2,
                    float* __restrict__ out) {
    int g = blockIdx.x;
    int beg = g_gstart[g], end = g_gstart[g + 1];
    int tid = threadIdx.x;
    __shared__ float pooled[256];
    __shared__ float hsm[256];
    __shared__ float partial[4];

    float s = 0.0f;
    for (int n = beg; n < end; n++)
        s += __half2float(xf[(size_t)n * 256 + tid]);
    float cnt = fmaxf((float)(end - beg), 1.0f);
    pooled[tid] = s / cnt;
    __syncthreads();

    int j = tid & 127, half = tid >> 7;
    float acc = 0.0f;
    const float* w = Wp1 + (size_t)(half * 128) * 128 + j;
#pragma unroll 8
    for (int k = 0; k < 128; k++) acc = fmaf(pooled[half * 128 + k], w[k * 128], acc);
    hsm[tid] = acc;
    __syncthreads();
    if (tid < 128) {
        float h = fmaxf(hsm[tid] + hsm[tid + 128] + bp1[tid], 0.0f) * Wp2[tid];
#pragma unroll
        for (int o = 16; o; o >>= 1) h += __shfl_down_sync(0xffffffffu, h, o);
        if ((tid & 31) == 0) partial[tid >> 5] = h;
    }
    __syncthreads();
    if (tid == 0)
        out[g] = partial[0] + partial[1] + partial[2] + partial[3] + bp2[0];
}

// ---------------- launcher ----------------
extern "C" void kernel_launch(void* const* d_in, const int* in_sizes, int n_in,
                              void* d_out, int out_size) {
    const float* x     = (const float*)d_in[0];
    const int*   ei    = (const int*)  d_in[1];
    const float* ea    = (const float*)d_in[2];
    const int*   batch = (const int*)  d_in[3];
    const float* Wl    = (const float*)d_in[4];
    const float* bl    = (const float*)d_in[5];
    const float* Wr    = (const float*)d_in[6];
    const float* br    = (const float*)d_in[7];
    const float* We    = (const float*)d_in[8];
    const float* att   = (const float*)d_in[9];
    const float* bias  = (const float*)d_in[10];
    const float* Wp1   = (const float*)d_in[11];
    const float* bp1   = (const float*)d_in[12];
    const float* Wp2   = (const float*)d_in[13];
    const float* bp2   = (const float*)d_in[14];
    float* out = (float*)d_out;
    const int* src = ei;
    const int* dst = ei + NEDGES;

    float *esum, *eloop;
    __half *x16, *b16A, *b16B, *xl, *xr, *wlt, *wrt, *wet;
    int* cnt;
    cudaGetSymbolAddress((void**)&x16,  g_x16);
    cudaGetSymbolAddress((void**)&b16A, g_buf16A);
    cudaGetSymbolAddress((void**)&b16B, g_buf16B);
    cudaGetSymbolAddress((void**)&xl,   g_xl);
    cudaGetSymbolAddress((void**)&xr,   g_xr);
    cudaGetSymbolAddress((void**)&wlt,  g_wlt);
    cudaGetSymbolAddress((void**)&wrt,  g_wrt);
    cudaGetSymbolAddress((void**)&wet,  g_wet);
    cudaGetSymbolAddress((void**)&esum, g_esum);
    cudaGetSymbolAddress((void**)&eloop, g_eloop);
    cudaGetSymbolAddress((void**)&cnt,  g_cnt);

    // ---- CSR build + conversions ----
    cudaMemsetAsync(cnt, 0, NNODES * sizeof(int));
    hist_kernel<<<(NEDGES + 255) / 256, 256>>>(dst);
    blocksum_kernel<<<NBLK, 256>>>();
    scanb_kernel<<<1, 512>>>();
    rowptr_kernel<<<NBLK, 256>>>();
    fill_kernel<<<(NEDGES + 255) / 256, 256>>>(src, dst);
    permute_ea_kernel<<<(NEDGES * 8 + 255) / 256, 256>>>(ea);
    gbounds_kernel<<<(GDIM + 256) / 256, 256>>>(batch);

    convx_kernel<<<(NNODES * 32 + 255) / 256, 256>>>(x);
    dim3 tb(32, 8);
    convw_kernel<<<dim3(8, 8, 3), tb>>>(Wl, wlt, 256);
    convw_kernel<<<dim3(8, 8, 3), tb>>>(Wr, wrt, 256);
    convw_kernel<<<dim3(8, 2, 3), tb>>>(We, wet, 64);

    cudaMemsetAsync(esum, 0, EDIM * sizeof(float));
    esum_kernel<<<512, 256>>>(ea);
    eloop_kernel<<<NLAYER, 256>>>(We);

    const __half* xcur = x16;
    for (int l = 0; l < NLAYER; l++) {
        __half* xn = (l & 1) ? b16B : b16A;
        dim3 gN((NNODES + 127) / 128, 4);
        gemm_node<<<gN, 256>>>(xcur, wlt + (size_t)l * 256 * 256, wrt + (size_t)l * 256 * 256,
                               bl + l * 256, br + l * 256, xl, xr, NNODES);
        // chunked edge phase: keep each eproj chunk L2-resident between producer/consumer
        dim3 gE((NEDGES + 127) / 128, 2);
        for (int c = 0; c < NCHUNK; c++) {
            int nlo = c * NPC;
            int nhi = (c + 1 == NCHUNK) ? NNODES : (c + 1) * NPC;
            gemm_edge<<<gE, 256>>>(wet + (size_t)l * 64 * 256, nlo, nhi);
            int nodes = nhi - nlo;
            fused_gat_kernel<<<(nodes * 32 + 255) / 256, 256>>>(
                att + l * 256, bias + l * 256, eloop + l * 256, xn, nlo, nhi);
        }
        xcur = xn;
    }

    poolmlp_kernel<<<GDIM, 256>>>(xcur, Wp1, bp1, Wp2, bp2, out);
}

// round 15
// speedup vs baseline: 1.0957x; 1.0957x over previous
#include <cuda_runtime.h>
#include <cuda_fp16.h>
#include <cuda_bf16.h>
#include <cstdint>

#define NNODES 100000
#define NEDGES 300000
#define GDIM   2048
#define HIDDIM 256
#define EDIM   64
#define NLAYER 3
#define NBLK   ((NNODES + 255) / 256)   // 391

// ---------------- static device scratch ----------------
__device__ __half g_x16[(size_t)NNODES * HIDDIM];
__device__ __half g_buf16A[(size_t)NNODES * HIDDIM];
__device__ __half g_buf16B[(size_t)NNODES * HIDDIM];
__device__ __half g_xl[(size_t)NNODES * HIDDIM];
__device__ __half g_xr[(size_t)NNODES * HIDDIM];
__device__ __half g_eproj[(size_t)NEDGES * HIDDIM];     // CSR-sorted order, streaming
__device__ __half g_ea16[(size_t)NEDGES * EDIM];        // edge_attr fp16, CSR order
__device__ __half g_wlt[(size_t)NLAYER * HIDDIM * HIDDIM];
__device__ __half g_wrt[(size_t)NLAYER * HIDDIM * HIDDIM];
__device__ __half g_wet[(size_t)NLAYER * HIDDIM * EDIM];
__device__ float g_eloop[NLAYER * HIDDIM];
__device__ float g_esum[EDIM];
// CSR (dst-sorted edges)
__device__ int g_cnt[NNODES];
__device__ int g_bsum[512];
__device__ int g_rowptr[NNODES + 1];
__device__ int g_woff[NNODES];
__device__ int g_ssrc[NEDGES];
__device__ int g_seid[NEDGES];
__device__ int g_gstart[GDIM + 1];

// ---------------- helpers ----------------
__device__ __forceinline__ void mma_f16(float* c, const uint32_t* a, const uint32_t* b) {
    asm volatile("mma.sync.aligned.m16n8k16.row.col.f32.f16.f16.f32 "
                 "{%0,%1,%2,%3}, {%4,%5,%6,%7}, {%8,%9}, {%0,%1,%2,%3};"
                 : "+f"(c[0]), "+f"(c[1]), "+f"(c[2]), "+f"(c[3])
                 : "r"(a[0]), "r"(a[1]), "r"(a[2]), "r"(a[3]), "r"(b[0]), "r"(b[1]));
}
__device__ __forceinline__ void cp16(void* smem, const void* gmem) {
    uint32_t s;
    asm("{ .reg .u64 t; cvta.to.shared.u64 t, %1; cvt.u32.u64 %0, t; }" : "=r"(s) : "l"(smem));
    asm volatile("cp.async.cg.shared.global [%0], [%1], 16;" :: "r"(s), "l"(gmem));
}
__device__ __forceinline__ int swz(int row, int col) {
    return ((((col >> 3) ^ ((row >> 1) & 3)) << 3) | (col & 7));
}
__device__ __forceinline__ uint4 pack8h(float4 a, float4 b) {
    uint4 u;
    *(__half2*)&u.x = __floats2half2_rn(a.x, a.y);
    *(__half2*)&u.y = __floats2half2_rn(a.z, a.w);
    *(__half2*)&u.z = __floats2half2_rn(b.x, b.y);
    *(__half2*)&u.w = __floats2half2_rn(b.z, b.w);
    return u;
}
__device__ __forceinline__ void fp16x8_expand(uint4 u, float4& o0, float4& o1) {
    float2 f0 = __half22float2(*(__half2*)&u.x);
    float2 f1 = __half22float2(*(__half2*)&u.y);
    float2 f2 = __half22float2(*(__half2*)&u.z);
    float2 f3 = __half22float2(*(__half2*)&u.w);
    o0 = make_float4(f0.x, f0.y, f1.x, f1.y);
    o1 = make_float4(f2.x, f2.y, f3.x, f3.y);
}
// streaming (cache-streaming .cs, evict-first semantics) store/load for the eproj stream
__device__ __forceinline__ void st_stream_b32(void* p, uint32_t v) {
    asm volatile("st.global.cs.b32 [%0], %1;" :: "l"(p), "r"(v) : "memory");
}
__device__ __forceinline__ uint4 ld_stream_v4(const void* p) {
    uint4 u;
    asm volatile("ld.global.cs.v4.u32 {%0,%1,%2,%3}, [%4];"
                 : "=r"(u.x), "=r"(u.y), "=r"(u.z), "=r"(u.w) : "l"(p));
    return u;
}

// ========== fp16 GEMM: cp.async 2-stage, BK=32, CTA 128x128, 8 warps 4x2 ==========
#define GEMM_LOAD16(s, k0, Ap, Bp, K, M, row0, col0)                                  \
    _Pragma("unroll") for (int i = 0; i < 2; i++) {                                   \
        int idx = tid + i * 256;                                                      \
        int r = idx >> 2, q = (idx & 3) * 8;                                          \
        int ar = (row0) + r; if (ar >= (M)) ar = (M) - 1;                             \
        cp16(&As[s][r][swz(r, q)], (Ap) + (size_t)ar * (K) + (k0) + q);               \
        cp16(&Bs[s][r][swz(r, q)], (Bp) + (size_t)((col0) + r) * (K) + (k0) + q);     \
    }                                                                                 \
    asm volatile("cp.async.commit_group;" ::: "memory");

#define GEMM_BODY16(Ap, Bp, K, M, row0, col0)                                          \
    float acc[2][8][4];                                                               \
    _Pragma("unroll") for (int mt = 0; mt < 2; mt++)                                  \
    _Pragma("unroll") for (int nt = 0; nt < 8; nt++)                                  \
    _Pragma("unroll") for (int i = 0; i < 4; i++) acc[mt][nt][i] = 0.0f;              \
    GEMM_LOAD16(0, 0, Ap, Bp, K, M, row0, col0)                                       \
    const int NKC = (K) / 32;                                                         \
    for (int kc = 0; kc < NKC; kc++) {                                                \
        if (kc + 1 < NKC) {                                                           \
            GEMM_LOAD16((kc + 1) & 1, (kc + 1) * 32, Ap, Bp, K, M, row0, col0)        \
            asm volatile("cp.async.wait_group 1;" ::: "memory");                      \
        } else {                                                                      \
            asm volatile("cp.async.wait_group 0;" ::: "memory");                      \
        }                                                                             \
        __syncthreads();                                                              \
        const int st = kc & 1;                                                        \
        _Pragma("unroll") for (int ks = 0; ks < 2; ks++) {                            \
            const int kb = ks * 16;                                                   \
            uint32_t bf[8][2];                                                        \
            _Pragma("unroll") for (int nt = 0; nt < 8; nt++) {                        \
                const int bn = warp_n * 64 + nt * 8 + lq;                             \
                bf[nt][0] = *(const uint32_t*)&Bs[st][bn][swz(bn, kb + lr * 2)];      \
                bf[nt][1] = *(const uint32_t*)&Bs[st][bn][swz(bn, kb + lr * 2 + 8)];  \
            }                                                                         \
            _Pragma("unroll") for (int mt = 0; mt < 2; mt++) {                        \
                const int ar = warp_m * 32 + mt * 16 + lq;                            \
                uint32_t af[4];                                                       \
                af[0] = *(const uint32_t*)&As[st][ar][swz(ar, kb + lr * 2)];          \
                af[1] = *(const uint32_t*)&As[st][ar + 8][swz(ar + 8, kb + lr * 2)];  \
                af[2] = *(const uint32_t*)&As[st][ar][swz(ar, kb + lr * 2 + 8)];      \
                af[3] = *(const uint32_t*)&As[st][ar + 8][swz(ar + 8, kb + lr * 2 + 8)]; \
                _Pragma("unroll") for (int nt = 0; nt < 8; nt++)                      \
                    mma_f16(acc[mt][nt], af, bf[nt]);                                 \
            }                                                                         \
        }                                                                             \
        __syncthreads();                                                              \
    }

// ---------------- fused node GEMM ----------------
__global__ __launch_bounds__(256)
void gemm_node(const __half* __restrict__ A,
               const __half* __restrict__ Wlt, const __half* __restrict__ Wrt,
               const float* __restrict__ bl_, const float* __restrict__ br_,
               __half* __restrict__ Cl, __half* __restrict__ Cr, int M) {
    __shared__ __align__(16) __half As[2][128][32];
    __shared__ __align__(16) __half Bs[2][128][32];
    const int tid = threadIdx.x, warp = tid >> 5, lane = tid & 31;
    const int warp_m = warp & 3, warp_n = warp >> 2;
    const int row0 = blockIdx.x * 128;
    const int col0 = (blockIdx.y & 1) * 128;
    const __half* W   = (blockIdx.y < 2) ? Wlt : Wrt;
    const float* bias = (blockIdx.y < 2) ? bl_ : br_;
    __half* C         = (blockIdx.y < 2) ? Cl  : Cr;
    const int lq = lane >> 2, lr = lane & 3;

    GEMM_BODY16(A, W, 256, M, row0, col0)

    const int r_base = row0 + warp_m * 32 + lq;
    const int c_base = col0 + warp_n * 64 + lr * 2;
#pragma unroll
    for (int nt = 0; nt < 8; nt++) {
        int c = c_base + nt * 8;
        float2 bv = *(const float2*)(bias + c);
#pragma unroll
        for (int mt = 0; mt < 2; mt++) {
            int r = r_base + mt * 16;
            if (r < M) {
                __half2 v = __floats2half2_rn(acc[mt][nt][0] + bv.x, acc[mt][nt][1] + bv.y);
                *(__half2*)(C + (size_t)r * 256 + c) = v;
            }
            if (r + 8 < M) {
                __half2 v = __floats2half2_rn(acc[mt][nt][2] + bv.x, acc[mt][nt][3] + bv.y);
                *(__half2*)(C + (size_t)(r + 8) * 256 + c) = v;
            }
        }
    }
}

// ---------------- edge GEMM: eproj stored with .cs (streaming) ----------------
__global__ __launch_bounds__(256)
void gemm_edge(const __half* __restrict__ Wet) {
    __shared__ __align__(16) __half As[2][128][32];
    __shared__ __align__(16) __half Bs[2][128][32];
    const __half* A = g_ea16;
    const int tid = threadIdx.x, warp = tid >> 5, lane = tid & 31;
    const int warp_m = warp & 3, warp_n = warp >> 2;
    const int row0 = blockIdx.x * 128;
    const int col0 = blockIdx.y * 128;
    const int lq = lane >> 2, lr = lane & 3;
    const int M = NEDGES;

    GEMM_BODY16(A, Wet, 64, M, row0, col0)

    const int r_base = row0 + warp_m * 32 + lq;
    const int c_base = col0 + warp_n * 64 + lr * 2;
#pragma unroll
    for (int nt = 0; nt < 8; nt++) {
        int c = c_base + nt * 8;
#pragma unroll
        for (int mt = 0; mt < 2; mt++) {
            int r = r_base + mt * 16;
            if (r < M) {
                __half2 v = __floats2half2_rn(acc[mt][nt][0], acc[mt][nt][1]);
                st_stream_b32(g_eproj + (size_t)r * 256 + c, *(uint32_t*)&v);
            }
            if (r + 8 < M) {
                __half2 v = __floats2half2_rn(acc[mt][nt][2], acc[mt][nt][3]);
                st_stream_b32(g_eproj + (size_t)(r + 8) * 256 + c, *(uint32_t*)&v);
            }
        }
    }
}

// ---------------- conversion kernels ----------------
__global__ void convx_kernel(const float* __restrict__ x) {
    int i = blockIdx.x * blockDim.x + threadIdx.x;
    if (i >= NNODES * 32) return;
    const float4* s = (const float4*)x + (size_t)i * 2;
    ((uint4*)g_x16)[i] = pack8h(s[0], s[1]);
}
__global__ void convw_kernel(const float* __restrict__ W, __half* __restrict__ Wt, int K) {
    __shared__ float t[32][33];
    int l = blockIdx.z;
    const float* Wl = W + (size_t)l * K * 256;
    __half* Wtl = Wt + (size_t)l * K * 256;
    int n0 = blockIdx.x * 32, k0 = blockIdx.y * 32;
    int tx = threadIdx.x, ty = threadIdx.y;
#pragma unroll
    for (int j = 0; j < 32; j += 8) t[ty + j][tx] = Wl[(size_t)(k0 + ty + j) * 256 + n0 + tx];
    __syncthreads();
#pragma unroll
    for (int j = 0; j < 32; j += 8)
        Wtl[(size_t)(n0 + ty + j) * K + k0 + tx] = __float2half(t[tx][ty + j]);
}

// ---------------- CSR build ----------------
__global__ void hist_kernel(const int* __restrict__ dst) {
    int e = blockIdx.x * blockDim.x + threadIdx.x;
    if (e < NEDGES) atomicAdd(&g_cnt[dst[e]], 1);
}
__global__ void blocksum_kernel() {
    int i = blockIdx.x * 256 + threadIdx.x;
    int v = (i < NNODES) ? g_cnt[i] : 0;
    __shared__ int ws[8];
#pragma unroll
    for (int o = 16; o; o >>= 1) v += __shfl_down_sync(0xffffffffu, v, o);
    if ((threadIdx.x & 31) == 0) ws[threadIdx.x >> 5] = v;
    __syncthreads();
    if (threadIdx.x == 0) {
        int s = 0;
#pragma unroll
        for (int j = 0; j < 8; j++) s += ws[j];
        g_bsum[blockIdx.x] = s;
    }
}
__global__ void scanb_kernel() {
    __shared__ int sm[512];
    int i = threadIdx.x;
    int v = (i < NBLK) ? g_bsum[i] : 0;
    sm[i] = v;
    __syncthreads();
    for (int s = 1; s < 512; s <<= 1) {
        int t = (i >= s) ? sm[i - s] : 0;
        __syncthreads();
        sm[i] += t;
        __syncthreads();
    }
    if (i < NBLK) g_bsum[i] = sm[i] - v;
}
__global__ void rowptr_kernel() {
    int tid = threadIdx.x;
    int i = blockIdx.x * 256 + tid;
    int v = (i < NNODES) ? g_cnt[i] : 0;
    __shared__ int sm[256];
    sm[tid] = v;
    __syncthreads();
    for (int s = 1; s < 256; s <<= 1) {
        int t = (tid >= s) ? sm[tid - s] : 0;
        __syncthreads();
        sm[tid] += t;
        __syncthreads();
    }
    int ex = sm[tid] - v + g_bsum[blockIdx.x];
    if (i < NNODES) { g_rowptr[i] = ex; g_woff[i] = ex; }
    if (i == NNODES - 1) g_rowptr[NNODES] = NEDGES;
}
__global__ void fill_kernel(const int* __restrict__ src, const int* __restrict__ dst) {
    int e = blockIdx.x * blockDim.x + threadIdx.x;
    if (e >= NEDGES) return;
    int d = dst[e];
    int pos = atomicAdd(&g_woff[d], 1);
    g_ssrc[pos] = src[e];
    g_seid[pos] = e;
}
__global__ void permute_ea_kernel(const float* __restrict__ ea) {
    int gt = blockIdx.x * blockDim.x + threadIdx.x;
    if (gt >= NEDGES * 8) return;
    int i = gt >> 3, q = gt & 7;
    int e = g_seid[i];
    const float4* s = (const float4*)(ea + (size_t)e * 64 + q * 8);
    ((uint4*)g_ea16)[(size_t)i * 8 + q] = pack8h(s[0], s[1]);
}
__global__ void gbounds_kernel(const int* __restrict__ batch) {
    int g = blockIdx.x * blockDim.x + threadIdx.x;
    if (g > GDIM) return;
    int lo = 0, hi = NNODES;
    while (lo < hi) {
        int mid = (lo + hi) >> 1;
        if (batch[mid] < g) lo = mid + 1; else hi = mid;
    }
    g_gstart[g] = lo;
}

// ---------------- edge_attr column sums + eloop ----------------
__global__ void esum_kernel(const float* __restrict__ ea) {
    int col = threadIdx.x & 63;
    int rowsPerBlk = blockDim.x >> 6;
    int r0 = blockIdx.x * rowsPerBlk + (threadIdx.x >> 6);
    int rstride = gridDim.x * rowsPerBlk;
    float s = 0.0f;
    for (int r = r0; r < NEDGES; r += rstride) s += ea[(size_t)r * EDIM + col];
    atomicAdd(&g_esum[col], s);
}
__global__ void eloop_kernel(const float* __restrict__ We) {
    int l = blockIdx.x;
    int j = threadIdx.x;
    const float* W = We + (size_t)l * EDIM * 256;
    const float inv = 1.0f / (float)NEDGES;
    float acc = 0.0f;
#pragma unroll
    for (int k = 0; k < EDIM; k++) acc = fmaf(g_esum[k] * inv, W[k * 256 + j], acc);
    g_eloop[l * 256 + j] = acc;
}

// ---------------- fused GAT edge phase ----------------
__global__ __launch_bounds__(256)
void fused_gat_kernel(const float* __restrict__ att, const float* __restrict__ bias,
                      const float* __restrict__ eloop, __half* __restrict__ xn) {
    int gt = blockIdx.x * blockDim.x + threadIdx.x;
    int d = gt >> 5, lane = gt & 31;
    if (d >= NNODES) return;
    const int off = lane * 8;

    float4 xr0, xr1;
    fp16x8_expand(*(const uint4*)(g_xr + (size_t)d * 256 + off), xr0, xr1);
    float4 at0 = *(const float4*)(att + off);
    float4 at1 = *(const float4*)(att + off + 4);

    float acc[8];
    float denom;
    {
        float4 a0, a1;
        fp16x8_expand(*(const uint4*)(g_xl + (size_t)d * 256 + off), a0, a1);
        float4 e0 = *(const float4*)(eloop + off);
        float4 e1 = *(const float4*)(eloop + off + 4);
        float t = 0.0f, m;
        m = a0.x + xr0.x + e0.x; m = fmaxf(m, 0.2f * m); t = fmaf(m, at0.x, t);
        m = a0.y + xr0.y + e0.y; m = fmaxf(m, 0.2f * m); t = fmaf(m, at0.y, t);
        m = a0.z + xr0.z + e0.z; m = fmaxf(m, 0.2f * m); t = fmaf(m, at0.z, t);
        m = a0.w + xr0.w + e0.w; m = fmaxf(m, 0.2f * m); t = fmaf(m, at0.w, t);
        m = a1.x + xr1.x + e1.x; m = fmaxf(m, 0.2f * m); t = fmaf(m, at1.x, t);
        m = a1.y + xr1.y + e1.y; m = fmaxf(m, 0.2f * m); t = fmaf(m, at1.y, t);
        m = a1.z + xr1.z + e1.z; m = fmaxf(m, 0.2f * m); t = fmaf(m, at1.z, t);
        m = a1.w + xr1.w + e1.w; m = fmaxf(m, 0.2f * m); t = fmaf(m, at1.w, t);
        t += __shfl_down_sync(0xffffffffu, t, 4, 8);
        t += __shfl_down_sync(0xffffffffu, t, 2, 8);
        t += __shfl_down_sync(0xffffffffu, t, 1, 8);
        float p = __expf(__shfl_sync(0xffffffffu, t, 0, 8));
        denom = p;
        acc[0] = p * a0.x; acc[1] = p * a0.y; acc[2] = p * a0.z; acc[3] = p * a0.w;
        acc[4] = p * a1.x; acc[5] = p * a1.y; acc[6] = p * a1.z; acc[7] = p * a1.w;
    }
    const int beg = g_rowptr[d], end = g_rowptr[d + 1];
    uint4 au, eu;
    if (beg < end) {
        int s = g_ssrc[beg];
        au = *(const uint4*)(g_xl + (size_t)s * 256 + off);
        eu = ld_stream_v4(g_eproj + (size_t)beg * 256 + off);
    }
    for (int i = beg; i < end; i++) {
        uint4 a_cur = au, e_cur = eu;
        if (i + 1 < end) {
            int s = g_ssrc[i + 1];
            au = *(const uint4*)(g_xl + (size_t)s * 256 + off);
            eu = ld_stream_v4(g_eproj + (size_t)(i + 1) * 256 + off);
        }
        float4 a0, a1, e0, e1;
        fp16x8_expand(a_cur, a0, a1);
        fp16x8_expand(e_cur, e0, e1);
        float t = 0.0f, m;
        m = a0.x + xr0.x + e0.x; m = fmaxf(m, 0.2f * m); t = fmaf(m, at0.x, t);
        m = a0.y + xr0.y + e0.y; m = fmaxf(m, 0.2f * m); t = fmaf(m, at0.y, t);
        m = a0.z + xr0.z + e0.z; m = fmaxf(m, 0.2f * m); t = fmaf(m, at0.z, t);
        m = a0.w + xr0.w + e0.w; m = fmaxf(m, 0.2f * m); t = fmaf(m, at0.w, t);
        m = a1.x + xr1.x + e1.x; m = fmaxf(m, 0.2f * m); t = fmaf(m, at1.x, t);
        m = a1.y + xr1.y + e1.y; m = fmaxf(m, 0.2f * m); t = fmaf(m, at1.y, t);
        m = a1.z + xr1.z + e1.z; m = fmaxf(m, 0.2f * m); t = fmaf(m, at1.z, t);
        m = a1.w + xr1.w + e1.w; m = fmaxf(m, 0.2f * m); t = fmaf(m, at1.w, t);
        t += __shfl_down_sync(0xffffffffu, t, 4, 8);
        t += __shfl_down_sync(0xffffffffu, t, 2, 8);
        t += __shfl_down_sync(0xffffffffu, t, 1, 8);
        float p = __expf(__shfl_sync(0xffffffffu, t, 0, 8));
        denom += p;
        acc[0] = fmaf(p, a0.x, acc[0]); acc[1] = fmaf(p, a0.y, acc[1]);
        acc[2] = fmaf(p, a0.z, acc[2]); acc[3] = fmaf(p, a0.w, acc[3]);
        acc[4] = fmaf(p, a1.x, acc[4]); acc[5] = fmaf(p, a1.y, acc[5]);
        acc[6] = fmaf(p, a1.z, acc[6]); acc[7] = fmaf(p, a1.w, acc[7]);
    }
    float inv = 1.0f / (denom + 1e-16f);
    float4 b0 = *(const float4*)(bias + off);
    float4 b1 = *(const float4*)(bias + off + 4);
    float4 o0, o1;
    o0.x = fmaxf(fmaf(acc[0], inv, b0.x), 0.f); o0.y = fmaxf(fmaf(acc[1], inv, b0.y), 0.f);
    o0.z = fmaxf(fmaf(acc[2], inv, b0.z), 0.f); o0.w = fmaxf(fmaf(acc[3], inv, b0.w), 0.f);
    o1.x = fmaxf(fmaf(acc[4], inv, b1.x), 0.f); o1.y = fmaxf(fmaf(acc[5], inv, b1.y), 0.f);
    o1.z = fmaxf(fmaf(acc[6], inv, b1.z), 0.f); o1.w = fmaxf(fmaf(acc[7], inv, b1.w), 0.f);
    *(uint4*)(xn + (size_t)d * 256 + off) = pack8h(o0, o1);
}

// ---------------- fused pool + MLP: one block per graph (batch is sorted) ----------------
__global__ __launch_bounds__(256)
void poolmlp_kernel(const __half* __restrict__ xf,
                    const float* __restrict__ Wp1, const float* __restrict__ bp1,
                    const float* __restrict__ Wp2, const float* __restrict__ bp2,
                    float* __restrict__ out) {
    int g = blockIdx.x;
    int beg = g_gstart[g], end = g_gstart[g + 1];
    int tid = threadIdx.x;
    __shared__ float pooled[256];
    __shared__ float hsm[256];
    __shared__ float partial[4];

    float s = 0.0f;
    for (int n = beg; n < end; n++)
        s += __half2float(xf[(size_t)n * 256 + tid]);
    float cnt = fmaxf((float)(end - beg), 1.0f);
    pooled[tid] = s / cnt;
    __syncthreads();

    int j = tid & 127, half = tid >> 7;
    float acc = 0.0f;
    const float* w = Wp1 + (size_t)(half * 128) * 128 + j;
#pragma unroll 8
    for (int k = 0; k < 128; k++) acc = fmaf(pooled[half * 128 + k], w[k * 128], acc);
    hsm[tid] = acc;
    __syncthreads();
    if (tid < 128) {
        float h = fmaxf(hsm[tid] + hsm[tid + 128] + bp1[tid], 0.0f) * Wp2[tid];
#pragma unroll
        for (int o = 16; o; o >>= 1) h += __shfl_down_sync(0xffffffffu, h, o);
        if ((tid & 31) == 0) partial[tid >> 5] = h;
    }
    __syncthreads();
    if (tid == 0)
        out[g] = partial[0] + partial[1] + partial[2] + partial[3] + bp2[0];
}

// ---------------- launcher ----------------
extern "C" void kernel_launch(void* const* d_in, const int* in_sizes, int n_in,
                              void* d_out, int out_size) {
    const float* x     = (const float*)d_in[0];
    const int*   ei    = (const int*)  d_in[1];
    const float* ea    = (const float*)d_in[2];
    const int*   batch = (const int*)  d_in[3];
    const float* Wl    = (const float*)d_in[4];
    const float* bl    = (const float*)d_in[5];
    const float* Wr    = (const float*)d_in[6];
    const float* br    = (const float*)d_in[7];
    const float* We    = (const float*)d_in[8];
    const float* att   = (const float*)d_in[9];
    const float* bias  = (const float*)d_in[10];
    const float* Wp1   = (const float*)d_in[11];
    const float* bp1   = (const float*)d_in[12];
    const float* Wp2   = (const float*)d_in[13];
    const float* bp2   = (const float*)d_in[14];
    float* out = (float*)d_out;
    const int* src = ei;
    const int* dst = ei + NEDGES;

    float *esum, *eloop;
    __half *x16, *b16A, *b16B, *xl, *xr, *wlt, *wrt, *wet;
    int* cnt;
    cudaGetSymbolAddress((void**)&x16,  g_x16);
    cudaGetSymbolAddress((void**)&b16A, g_buf16A);
    cudaGetSymbolAddress((void**)&b16B, g_buf16B);
    cudaGetSymbolAddress((void**)&xl,   g_xl);
    cudaGetSymbolAddress((void**)&xr,   g_xr);
    cudaGetSymbolAddress((void**)&wlt,  g_wlt);
    cudaGetSymbolAddress((void**)&wrt,  g_wrt);
    cudaGetSymbolAddress((void**)&wet,  g_wet);
    cudaGetSymbolAddress((void**)&esum, g_esum);
    cudaGetSymbolAddress((void**)&eloop, g_eloop);
    cudaGetSymbolAddress((void**)&cnt,  g_cnt);

    // ---- CSR build + conversions ----
    cudaMemsetAsync(cnt, 0, NNODES * sizeof(int));
    hist_kernel<<<(NEDGES + 255) / 256, 256>>>(dst);
    blocksum_kernel<<<NBLK, 256>>>();
    scanb_kernel<<<1, 512>>>();
    rowptr_kernel<<<NBLK, 256>>>();
    fill_kernel<<<(NEDGES + 255) / 256, 256>>>(src, dst);
    permute_ea_kernel<<<(NEDGES * 8 + 255) / 256, 256>>>(ea);
    gbounds_kernel<<<(GDIM + 256) / 256, 256>>>(batch);

    convx_kernel<<<(NNODES * 32 + 255) / 256, 256>>>(x);
    dim3 tb(32, 8);
    convw_kernel<<<dim3(8, 8, 3), tb>>>(Wl, wlt, 256);
    convw_kernel<<<dim3(8, 8, 3), tb>>>(Wr, wrt, 256);
    convw_kernel<<<dim3(8, 2, 3), tb>>>(We, wet, 64);

    cudaMemsetAsync(esum, 0, EDIM * sizeof(float));
    esum_kernel<<<512, 256>>>(ea);
    eloop_kernel<<<NLAYER, 256>>>(We);

    const __half* xcur = x16;
    for (int l = 0; l < NLAYER; l++) {
        __half* xn = (l & 1) ? b16B : b16A;
        dim3 gN((NNODES + 127) / 128, 4);
        gemm_node<<<gN, 256>>>(xcur, wlt + (size_t)l * 256 * 256, wrt + (size_t)l * 256 * 256,
                               bl + l * 256, br + l * 256, xl, xr, NNODES);
        dim3 gE((NEDGES + 127) / 128, 2);
        gemm_edge<<<gE, 256>>>(wet + (size_t)l * 64 * 256);

        fused_gat_kernel<<<(NNODES * 32 + 255) / 256, 256>>>(att + l * 256, bias + l * 256,
                                                             eloop + l * 256, xn);
        xcur = xn;
    }

    poolmlp_kernel<<<GDIM, 256>>>(xcur, Wp1, bp1, Wp2, bp2, out);
}

// round 16
// speedup vs baseline: 1.1121x; 1.0150x over previous
#include <cuda_runtime.h>
#include <cuda_fp16.h>
#include <cuda_bf16.h>
#include <cstdint>

#define NNODES 100000
#define NEDGES 300000
#define GDIM   2048
#define HIDDIM 256
#define EDIM   64
#define NLAYER 3
#define NBLK   ((NNODES + 255) / 256)   // 391

// ---------------- static device scratch ----------------
__device__ __half g_x16[(size_t)NNODES * HIDDIM];
__device__ __half g_buf16A[(size_t)NNODES * HIDDIM];
__device__ __half g_buf16B[(size_t)NNODES * HIDDIM];
__device__ __half g_xl[(size_t)NNODES * HIDDIM];
__device__ __half g_xr[(size_t)NNODES * HIDDIM];
__device__ __half g_eproj[NLAYER][(size_t)NEDGES * HIDDIM];  // per-layer, CSR order
__device__ __half g_ea16[(size_t)NEDGES * EDIM];
__device__ __half g_wlt[(size_t)NLAYER * HIDDIM * HIDDIM];
__device__ __half g_wrt[(size_t)NLAYER * HIDDIM * HIDDIM];
__device__ __half g_wet[(size_t)NLAYER * HIDDIM * EDIM];
__device__ float g_eloop[NLAYER * HIDDIM];
__device__ float g_esum[EDIM];
// CSR (dst-sorted edges)
__device__ int g_cnt[NNODES];
__device__ int g_bsum[512];
__device__ int g_rowptr[NNODES + 1];
__device__ int g_woff[NNODES];
__device__ int g_ssrc[NEDGES];
__device__ int g_seid[NEDGES];
__device__ int g_gstart[GDIM + 1];

// ---------------- helpers ----------------
__device__ __forceinline__ void mma_f16(float* c, const uint32_t* a, const uint32_t* b) {
    asm volatile("mma.sync.aligned.m16n8k16.row.col.f32.f16.f16.f32 "
                 "{%0,%1,%2,%3}, {%4,%5,%6,%7}, {%8,%9}, {%0,%1,%2,%3};"
                 : "+f"(c[0]), "+f"(c[1]), "+f"(c[2]), "+f"(c[3])
                 : "r"(a[0]), "r"(a[1]), "r"(a[2]), "r"(a[3]), "r"(b[0]), "r"(b[1]));
}
__device__ __forceinline__ void cp16(void* smem, const void* gmem) {
    uint32_t s;
    asm("{ .reg .u64 t; cvta.to.shared.u64 t, %1; cvt.u32.u64 %0, t; }" : "=r"(s) : "l"(smem));
    asm volatile("cp.async.cg.shared.global [%0], [%1], 16;" :: "r"(s), "l"(gmem));
}
__device__ __forceinline__ int swz(int row, int col) {
    return ((((col >> 3) ^ ((row >> 1) & 3)) << 3) | (col & 7));
}
__device__ __forceinline__ uint4 pack8h(float4 a, float4 b) {
    uint4 u;
    *(__half2*)&u.x = __floats2half2_rn(a.x, a.y);
    *(__half2*)&u.y = __floats2half2_rn(a.z, a.w);
    *(__half2*)&u.z = __floats2half2_rn(b.x, b.y);
    *(__half2*)&u.w = __floats2half2_rn(b.z, b.w);
    return u;
}
__device__ __forceinline__ void fp16x8_expand(uint4 u, float4& o0, float4& o1) {
    float2 f0 = __half22float2(*(__half2*)&u.x);
    float2 f1 = __half22float2(*(__half2*)&u.y);
    float2 f2 = __half22float2(*(__half2*)&u.z);
    float2 f3 = __half22float2(*(__half2*)&u.w);
    o0 = make_float4(f0.x, f0.y, f1.x, f1.y);
    o1 = make_float4(f2.x, f2.y, f3.x, f3.y);
}
__device__ __forceinline__ void st_stream_b32(void* p, uint32_t v) {
    asm volatile("st.global.cs.b32 [%0], %1;" :: "l"(p), "r"(v) : "memory");
}
__device__ __forceinline__ uint4 ld_stream_v4(const void* p) {
    uint4 u;
    asm volatile("ld.global.cs.v4.u32 {%0,%1,%2,%3}, [%4];"
                 : "=r"(u.x), "=r"(u.y), "=r"(u.z), "=r"(u.w) : "l"(p));
    return u;
}

// ========== fp16 GEMM: cp.async 2-stage, BK=32, CTA 128x128, 8 warps 4x2 ==========
#define GEMM_LOAD16(s, k0, Ap, Bp, K, M, row0, col0)                                  \
    _Pragma("unroll") for (int i = 0; i < 2; i++) {                                   \
        int idx = tid + i * 256;                                                      \
        int r = idx >> 2, q = (idx & 3) * 8;                                          \
        int ar = (row0) + r; if (ar >= (M)) ar = (M) - 1;                             \
        cp16(&As[s][r][swz(r, q)], (Ap) + (size_t)ar * (K) + (k0) + q);               \
        cp16(&Bs[s][r][swz(r, q)], (Bp) + (size_t)((col0) + r) * (K) + (k0) + q);     \
    }                                                                                 \
    asm volatile("cp.async.commit_group;" ::: "memory");

#define GEMM_BODY16(Ap, Bp, K, M, row0, col0)                                          \
    float acc[2][8][4];                                                               \
    _Pragma("unroll") for (int mt = 0; mt < 2; mt++)                                  \
    _Pragma("unroll") for (int nt = 0; nt < 8; nt++)                                  \
    _Pragma("unroll") for (int i = 0; i < 4; i++) acc[mt][nt][i] = 0.0f;              \
    GEMM_LOAD16(0, 0, Ap, Bp, K, M, row0, col0)                                       \
    const int NKC = (K) / 32;                                                         \
    for (int kc = 0; kc < NKC; kc++) {                                                \
        if (kc + 1 < NKC) {                                                           \
            GEMM_LOAD16((kc + 1) & 1, (kc + 1) * 32, Ap, Bp, K, M, row0, col0)        \
            asm volatile("cp.async.wait_group 1;" ::: "memory");                      \
        } else {                                                                      \
            asm volatile("cp.async.wait_group 0;" ::: "memory");                      \
        }                                                                             \
        __syncthreads();                                                              \
        const int st = kc & 1;                                                        \
        _Pragma("unroll") for (int ks = 0; ks < 2; ks++) {                            \
            const int kb = ks * 16;                                                   \
            uint32_t bf[8][2];                                                        \
            _Pragma("unroll") for (int nt = 0; nt < 8; nt++) {                        \
                const int bn = warp_n * 64 + nt * 8 + lq;                             \
                bf[nt][0] = *(const uint32_t*)&Bs[st][bn][swz(bn, kb + lr * 2)];      \
                bf[nt][1] = *(const uint32_t*)&Bs[st][bn][swz(bn, kb + lr * 2 + 8)];  \
            }                                                                         \
            _Pragma("unroll") for (int mt = 0; mt < 2; mt++) {                        \
                const int ar = warp_m * 32 + mt * 16 + lq;                            \
                uint32_t af[4];                                                       \
                af[0] = *(const uint32_t*)&As[st][ar][swz(ar, kb + lr * 2)];          \
                af[1] = *(const uint32_t*)&As[st][ar + 8][swz(ar + 8, kb + lr * 2)];  \
                af[2] = *(const uint32_t*)&As[st][ar][swz(ar, kb + lr * 2 + 8)];      \
                af[3] = *(const uint32_t*)&As[st][ar + 8][swz(ar + 8, kb + lr * 2 + 8)]; \
                _Pragma("unroll") for (int nt = 0; nt < 8; nt++)                      \
                    mma_f16(acc[mt][nt], af, bf[nt]);                                 \
            }                                                                         \
        }                                                                             \
        __syncthreads();                                                              \
    }

// ---------------- fused node GEMM ----------------
__global__ __launch_bounds__(256)
void gemm_node(const __half* __restrict__ A,
               const __half* __restrict__ Wlt, const __half* __restrict__ Wrt,
               const float* __restrict__ bl_, const float* __restrict__ br_,
               __half* __restrict__ Cl, __half* __restrict__ Cr, int M) {
    __shared__ __align__(16) __half As[2][128][32];
    __shared__ __align__(16) __half Bs[2][128][32];
    const int tid = threadIdx.x, warp = tid >> 5, lane = tid & 31;
    const int warp_m = warp & 3, warp_n = warp >> 2;
    const int row0 = blockIdx.x * 128;
    const int col0 = (blockIdx.y & 1) * 128;
    const __half* W   = (blockIdx.y < 2) ? Wlt : Wrt;
    const float* bias = (blockIdx.y < 2) ? bl_ : br_;
    __half* C         = (blockIdx.y < 2) ? Cl  : Cr;
    const int lq = lane >> 2, lr = lane & 3;

    GEMM_BODY16(A, W, 256, M, row0, col0)

    const int r_base = row0 + warp_m * 32 + lq;
    const int c_base = col0 + warp_n * 64 + lr * 2;
#pragma unroll
    for (int nt = 0; nt < 8; nt++) {
        int c = c_base + nt * 8;
        float2 bv = *(const float2*)(bias + c);
#pragma unroll
        for (int mt = 0; mt < 2; mt++) {
            int r = r_base + mt * 16;
            if (r < M) {
                __half2 v = __floats2half2_rn(acc[mt][nt][0] + bv.x, acc[mt][nt][1] + bv.y);
                *(__half2*)(C + (size_t)r * 256 + c) = v;
            }
            if (r + 8 < M) {
                __half2 v = __floats2half2_rn(acc[mt][nt][2] + bv.x, acc[mt][nt][3] + bv.y);
                *(__half2*)(C + (size_t)(r + 8) * 256 + c) = v;
            }
        }
    }
}

// ---------------- edge GEMM: eproj (per-layer buffer) stored with .cs ----------------
__global__ __launch_bounds__(256)
void gemm_edge(const __half* __restrict__ Wet, __half* __restrict__ eout) {
    __shared__ __align__(16) __half As[2][128][32];
    __shared__ __align__(16) __half Bs[2][128][32];
    const __half* A = g_ea16;
    const int tid = threadIdx.x, warp = tid >> 5, lane = tid & 31;
    const int warp_m = warp & 3, warp_n = warp >> 2;
    const int row0 = blockIdx.x * 128;
    const int col0 = blockIdx.y * 128;
    const int lq = lane >> 2, lr = lane & 3;
    const int M = NEDGES;

    GEMM_BODY16(A, Wet, 64, M, row0, col0)

    const int r_base = row0 + warp_m * 32 + lq;
    const int c_base = col0 + warp_n * 64 + lr * 2;
#pragma unroll
    for (int nt = 0; nt < 8; nt++) {
        int c = c_base + nt * 8;
#pragma unroll
        for (int mt = 0; mt < 2; mt++) {
            int r = r_base + mt * 16;
            if (r < M) {
                __half2 v = __floats2half2_rn(acc[mt][nt][0], acc[mt][nt][1]);
                st_stream_b32(eout + (size_t)r * 256 + c, *(uint32_t*)&v);
            }
            if (r + 8 < M) {
                __half2 v = __floats2half2_rn(acc[mt][nt][2], acc[mt][nt][3]);
                st_stream_b32(eout + (size_t)(r + 8) * 256 + c, *(uint32_t*)&v);
            }
        }
    }
}

// ---------------- conversion kernels ----------------
__global__ void convx_kernel(const float* __restrict__ x) {
    int i = blockIdx.x * blockDim.x + threadIdx.x;
    if (i >= NNODES * 32) return;
    const float4* s = (const float4*)x + (size_t)i * 2;
    ((uint4*)g_x16)[i] = pack8h(s[0], s[1]);
}
__global__ void convw_kernel(const float* __restrict__ W, __half* __restrict__ Wt, int K) {
    __shared__ float t[32][33];
    int l = blockIdx.z;
    const float* Wl = W + (size_t)l * K * 256;
    __half* Wtl = Wt + (size_t)l * K * 256;
    int n0 = blockIdx.x * 32, k0 = blockIdx.y * 32;
    int tx = threadIdx.x, ty = threadIdx.y;
#pragma unroll
    for (int j = 0; j < 32; j += 8) t[ty + j][tx] = Wl[(size_t)(k0 + ty + j) * 256 + n0 + tx];
    __syncthreads();
#pragma unroll
    for (int j = 0; j < 32; j += 8)
        Wtl[(size_t)(n0 + ty + j) * K + k0 + tx] = __float2half(t[tx][ty + j]);
}

// ---------------- CSR build ----------------
__global__ void hist_kernel(const int* __restrict__ dst) {
    int e = blockIdx.x * blockDim.x + threadIdx.x;
    if (e < NEDGES) atomicAdd(&g_cnt[dst[e]], 1);
}
__global__ void blocksum_kernel() {
    int i = blockIdx.x * 256 + threadIdx.x;
    int v = (i < NNODES) ? g_cnt[i] : 0;
    __shared__ int ws[8];
#pragma unroll
    for (int o = 16; o; o >>= 1) v += __shfl_down_sync(0xffffffffu, v, o);
    if ((threadIdx.x & 31) == 0) ws[threadIdx.x >> 5] = v;
    __syncthreads();
    if (threadIdx.x == 0) {
        int s = 0;
#pragma unroll
        for (int j = 0; j < 8; j++) s += ws[j];
        g_bsum[blockIdx.x] = s;
    }
}
__global__ void scanb_kernel() {
    __shared__ int sm[512];
    int i = threadIdx.x;
    int v = (i < NBLK) ? g_bsum[i] : 0;
    sm[i] = v;
    __syncthreads();
    for (int s = 1; s < 512; s <<= 1) {
        int t = (i >= s) ? sm[i - s] : 0;
        __syncthreads();
        sm[i] += t;
        __syncthreads();
    }
    if (i < NBLK) g_bsum[i] = sm[i] - v;
}
__global__ void rowptr_kernel() {
    int tid = threadIdx.x;
    int i = blockIdx.x * 256 + tid;
    int v = (i < NNODES) ? g_cnt[i] : 0;
    __shared__ int sm[256];
    sm[tid] = v;
    __syncthreads();
    for (int s = 1; s < 256; s <<= 1) {
        int t = (tid >= s) ? sm[tid - s] : 0;
        __syncthreads();
        sm[tid] += t;
        __syncthreads();
    }
    int ex = sm[tid] - v + g_bsum[blockIdx.x];
    if (i < NNODES) { g_rowptr[i] = ex; g_woff[i] = ex; }
    if (i == NNODES - 1) g_rowptr[NNODES] = NEDGES;
}
__global__ void fill_kernel(const int* __restrict__ src, const int* __restrict__ dst) {
    int e = blockIdx.x * blockDim.x + threadIdx.x;
    if (e >= NEDGES) return;
    int d = dst[e];
    int pos = atomicAdd(&g_woff[d], 1);
    g_ssrc[pos] = src[e];
    g_seid[pos] = e;
}
__global__ void permute_ea_kernel(const float* __restrict__ ea) {
    int gt = blockIdx.x * blockDim.x + threadIdx.x;
    if (gt >= NEDGES * 8) return;
    int i = gt >> 3, q = gt & 7;
    int e = g_seid[i];
    const float4* s = (const float4*)(ea + (size_t)e * 64 + q * 8);
    ((uint4*)g_ea16)[(size_t)i * 8 + q] = pack8h(s[0], s[1]);
}
__global__ void gbounds_kernel(const int* __restrict__ batch) {
    int g = blockIdx.x * blockDim.x + threadIdx.x;
    if (g > GDIM) return;
    int lo = 0, hi = NNODES;
    while (lo < hi) {
        int mid = (lo + hi) >> 1;
        if (batch[mid] < g) lo = mid + 1; else hi = mid;
    }
    g_gstart[g] = lo;
}

// ---------------- edge_attr column sums + eloop ----------------
__global__ void esum_kernel(const float* __restrict__ ea) {
    int col = threadIdx.x & 63;
    int rowsPerBlk = blockDim.x >> 6;
    int r0 = blockIdx.x * rowsPerBlk + (threadIdx.x >> 6);
    int rstride = gridDim.x * rowsPerBlk;
    float s = 0.0f;
    for (int r = r0; r < NEDGES; r += rstride) s += ea[(size_t)r * EDIM + col];
    atomicAdd(&g_esum[col], s);
}
__global__ void eloop_kernel(const float* __restrict__ We) {
    int l = blockIdx.x;
    int j = threadIdx.x;
    const float* W = We + (size_t)l * EDIM * 256;
    const float inv = 1.0f / (float)NEDGES;
    float acc = 0.0f;
#pragma unroll
    for (int k = 0; k < EDIM; k++) acc = fmaf(g_esum[k] * inv, W[k * 256 + j], acc);
    g_eloop[l * 256 + j] = acc;
}

// ---------------- fused GAT edge phase ----------------
__global__ __launch_bounds__(256)
void fused_gat_kernel(const float* __restrict__ att, const float* __restrict__ bias,
                      const float* __restrict__ eloop, const __half* __restrict__ eproj,
                      __half* __restrict__ xn) {
    int gt = blockIdx.x * blockDim.x + threadIdx.x;
    int d = gt >> 5, lane = gt & 31;
    if (d >= NNODES) return;
    const int off = lane * 8;

    float4 xr0, xr1;
    fp16x8_expand(*(const uint4*)(g_xr + (size_t)d * 256 + off), xr0, xr1);
    float4 at0 = *(const float4*)(att + off);
    float4 at1 = *(const float4*)(att + off + 4);

    float acc[8];
    float denom;
    {
        float4 a0, a1;
        fp16x8_expand(*(const uint4*)(g_xl + (size_t)d * 256 + off), a0, a1);
        float4 e0 = *(const float4*)(eloop + off);
        float4 e1 = *(const float4*)(eloop + off + 4);
        float t = 0.0f, m;
        m = a0.x + xr0.x + e0.x; m = fmaxf(m, 0.2f * m); t = fmaf(m, at0.x, t);
        m = a0.y + xr0.y + e0.y; m = fmaxf(m, 0.2f * m); t = fmaf(m, at0.y, t);
        m = a0.z + xr0.z + e0.z; m = fmaxf(m, 0.2f * m); t = fmaf(m, at0.z, t);
        m = a0.w + xr0.w + e0.w; m = fmaxf(m, 0.2f * m); t = fmaf(m, at0.w, t);
        m = a1.x + xr1.x + e1.x; m = fmaxf(m, 0.2f * m); t = fmaf(m, at1.x, t);
        m = a1.y + xr1.y + e1.y; m = fmaxf(m, 0.2f * m); t = fmaf(m, at1.y, t);
        m = a1.z + xr1.z + e1.z; m = fmaxf(m, 0.2f * m); t = fmaf(m, at1.z, t);
        m = a1.w + xr1.w + e1.w; m = fmaxf(m, 0.2f * m); t = fmaf(m, at1.w, t);
        t += __shfl_down_sync(0xffffffffu, t, 4, 8);
        t += __shfl_down_sync(0xffffffffu, t, 2, 8);
        t += __shfl_down_sync(0xffffffffu, t, 1, 8);
        float p = __expf(__shfl_sync(0xffffffffu, t, 0, 8));
        denom = p;
        acc[0] = p * a0.x; acc[1] = p * a0.y; acc[2] = p * a0.z; acc[3] = p * a0.w;
        acc[4] = p * a1.x; acc[5] = p * a1.y; acc[6] = p * a1.z; acc[7] = p * a1.w;
    }
    const int beg = g_rowptr[d], end = g_rowptr[d + 1];
    uint4 au, eu;
    if (beg < end) {
        int s = g_ssrc[beg];
        au = *(const uint4*)(g_xl + (size_t)s * 256 + off);
        eu = ld_stream_v4(eproj + (size_t)beg * 256 + off);
    }
    for (int i = beg; i < end; i++) {
        uint4 a_cur = au, e_cur = eu;
        if (i + 1 < end) {
            int s = g_ssrc[i + 1];
            au = *(const uint4*)(g_xl + (size_t)s * 256 + off);
            eu = ld_stream_v4(eproj + (size_t)(i + 1) * 256 + off);
        }
        float4 a0, a1, e0, e1;
        fp16x8_expand(a_cur, a0, a1);
        fp16x8_expand(e_cur, e0, e1);
        float t = 0.0f, m;
        m = a0.x + xr0.x + e0.x; m = fmaxf(m, 0.2f * m); t = fmaf(m, at0.x, t);
        m = a0.y + xr0.y + e0.y; m = fmaxf(m, 0.2f * m); t = fmaf(m, at0.y, t);
        m = a0.z + xr0.z + e0.z; m = fmaxf(m, 0.2f * m); t = fmaf(m, at0.z, t);
        m = a0.w + xr0.w + e0.w; m = fmaxf(m, 0.2f * m); t = fmaf(m, at0.w, t);
        m = a1.x + xr1.x + e1.x; m = fmaxf(m, 0.2f * m); t = fmaf(m, at1.x, t);
        m = a1.y + xr1.y + e1.y; m = fmaxf(m, 0.2f * m); t = fmaf(m, at1.y, t);
        m = a1.z + xr1.z + e1.z; m = fmaxf(m, 0.2f * m); t = fmaf(m, at1.z, t);
        m = a1.w + xr1.w + e1.w; m = fmaxf(m, 0.2f * m); t = fmaf(m, at1.w, t);
        t += __shfl_down_sync(0xffffffffu, t, 4, 8);
        t += __shfl_down_sync(0xffffffffu, t, 2, 8);
        t += __shfl_down_sync(0xffffffffu, t, 1, 8);
        float p = __expf(__shfl_sync(0xffffffffu, t, 0, 8));
        denom += p;
        acc[0] = fmaf(p, a0.x, acc[0]); acc[1] = fmaf(p, a0.y, acc[1]);
        acc[2] = fmaf(p, a0.z, acc[2]); acc[3] = fmaf(p, a0.w, acc[3]);
        acc[4] = fmaf(p, a1.x, acc[4]); acc[5] = fmaf(p, a1.y, acc[5]);
        acc[6] = fmaf(p, a1.z, acc[6]); acc[7] = fmaf(p, a1.w, acc[7]);
    }
    float inv = 1.0f / (denom + 1e-16f);
    float4 b0 = *(const float4*)(bias + off);
    float4 b1 = *(const float4*)(bias + off + 4);
    float4 o0, o1;
    o0.x = fmaxf(fmaf(acc[0], inv, b0.x), 0.f); o0.y = fmaxf(fmaf(acc[1], inv, b0.y), 0.f);
    o0.z = fmaxf(fmaf(acc[2], inv, b0.z), 0.f); o0.w = fmaxf(fmaf(acc[3], inv, b0.w), 0.f);
    o1.x = fmaxf(fmaf(acc[4], inv, b1.x), 0.f); o1.y = fmaxf(fmaf(acc[5], inv, b1.y), 0.f);
    o1.z = fmaxf(fmaf(acc[6], inv, b1.z), 0.f); o1.w = fmaxf(fmaf(acc[7], inv, b1.w), 0.f);
    *(uint4*)(xn + (size_t)d * 256 + off) = pack8h(o0, o1);
}

// ---------------- fused pool + MLP ----------------
__global__ __launch_bounds__(256)
void poolmlp_kernel(const __half* __restrict__ xf,
                    const float* __restrict__ Wp1, const float* __restrict__ bp1,
                    const float* __restrict__ Wp2, const float* __restrict__ bp2,
                    float* __restrict__ out) {
    int g = blockIdx.x;
    int beg = g_gstart[g], end = g_gstart[g + 1];
    int tid = threadIdx.x;
    __shared__ float pooled[256];
    __shared__ float hsm[256];
    __shared__ float partial[4];

    float s = 0.0f;
    for (int n = beg; n < end; n++)
        s += __half2float(xf[(size_t)n * 256 + tid]);
    float cnt = fmaxf((float)(end - beg), 1.0f);
    pooled[tid] = s / cnt;
    __syncthreads();

    int j = tid & 127, half = tid >> 7;
    float acc = 0.0f;
    const float* w = Wp1 + (size_t)(half * 128) * 128 + j;
#pragma unroll 8
    for (int k = 0; k < 128; k++) acc = fmaf(pooled[half * 128 + k], w[k * 128], acc);
    hsm[tid] = acc;
    __syncthreads();
    if (tid < 128) {
        float h = fmaxf(hsm[tid] + hsm[tid + 128] + bp1[tid], 0.0f) * Wp2[tid];
#pragma unroll
        for (int o = 16; o; o >>= 1) h += __shfl_down_sync(0xffffffffu, h, o);
        if ((tid & 31) == 0) partial[tid >> 5] = h;
    }
    __syncthreads();
    if (tid == 0)
        out[g] = partial[0] + partial[1] + partial[2] + partial[3] + bp2[0];
}

// ---------------- launcher (fork/join multi-stream capture) ----------------
extern "C" void kernel_launch(void* const* d_in, const int* in_sizes, int n_in,
                              void* d_out, int out_size) {
    const float* x     = (const float*)d_in[0];
    const int*   ei    = (const int*)  d_in[1];
    const float* ea    = (const float*)d_in[2];
    const int*   batch = (const int*)  d_in[3];
    const float* Wl    = (const float*)d_in[4];
    const float* bl    = (const float*)d_in[5];
    const float* Wr    = (const float*)d_in[6];
    const float* br    = (const float*)d_in[7];
    const float* We    = (const float*)d_in[8];
    const float* att   = (const float*)d_in[9];
    const float* bias  = (const float*)d_in[10];
    const float* Wp1   = (const float*)d_in[11];
    const float* bp1   = (const float*)d_in[12];
    const float* Wp2   = (const float*)d_in[13];
    const float* bp2   = (const float*)d_in[14];
    float* out = (float*)d_out;
    const int* src = ei;
    const int* dst = ei + NEDGES;

    float *esum, *eloop;
    __half *x16, *b16A, *b16B, *xl, *xr, *wlt, *wrt, *wet, *eproj;
    int* cnt;
    cudaGetSymbolAddress((void**)&x16,  g_x16);
    cudaGetSymbolAddress((void**)&b16A, g_buf16A);
    cudaGetSymbolAddress((void**)&b16B, g_buf16B);
    cudaGetSymbolAddress((void**)&xl,   g_xl);
    cudaGetSymbolAddress((void**)&xr,   g_xr);
    cudaGetSymbolAddress((void**)&wlt,  g_wlt);
    cudaGetSymbolAddress((void**)&wrt,  g_wrt);
    cudaGetSymbolAddress((void**)&wet,  g_wet);
    cudaGetSymbolAddress((void**)&eproj, g_eproj);
    cudaGetSymbolAddress((void**)&esum, g_esum);
    cudaGetSymbolAddress((void**)&eloop, g_eloop);
    cudaGetSymbolAddress((void**)&cnt,  g_cnt);

    // persistent side stream + events (created once; reused each call)
    static cudaStream_t s1 = nullptr;
    static cudaEvent_t evPrep = nullptr, evEdge[NLAYER] = {nullptr, nullptr, nullptr}, evJoin = nullptr;
    if (!s1) {
        cudaStreamCreateWithFlags(&s1, cudaStreamNonBlocking);
        cudaEventCreateWithFlags(&evPrep, cudaEventDisableTiming);
        for (int l = 0; l < NLAYER; l++) cudaEventCreateWithFlags(&evEdge[l], cudaEventDisableTiming);
        cudaEventCreateWithFlags(&evJoin, cudaEventDisableTiming);
    }

    // ---- prologue on default stream ----
    cudaMemsetAsync(cnt, 0, NNODES * sizeof(int));
    hist_kernel<<<(NEDGES + 255) / 256, 256>>>(dst);
    blocksum_kernel<<<NBLK, 256>>>();
    scanb_kernel<<<1, 512>>>();
    rowptr_kernel<<<NBLK, 256>>>();
    fill_kernel<<<(NEDGES + 255) / 256, 256>>>(src, dst);
    permute_ea_kernel<<<(NEDGES * 8 + 255) / 256, 256>>>(ea);
    gbounds_kernel<<<(GDIM + 256) / 256, 256>>>(batch);

    convx_kernel<<<(NNODES * 32 + 255) / 256, 256>>>(x);
    dim3 tb(32, 8);
    convw_kernel<<<dim3(8, 8, 3), tb>>>(Wl, wlt, 256);
    convw_kernel<<<dim3(8, 8, 3), tb>>>(Wr, wrt, 256);
    convw_kernel<<<dim3(8, 2, 3), tb>>>(We, wet, 64);

    cudaMemsetAsync(esum, 0, EDIM * sizeof(float));
    esum_kernel<<<512, 256>>>(ea);
    eloop_kernel<<<NLAYER, 256>>>(We);

    // ---- fork: edge GEMMs for all layers on side stream ----
    cudaEventRecord(evPrep, 0);
    cudaStreamWaitEvent(s1, evPrep, 0);
    dim3 gE((NEDGES + 127) / 128, 2);
    for (int l = 0; l < NLAYER; l++) {
        gemm_edge<<<gE, 256, 0, s1>>>(wet + (size_t)l * 64 * 256,
                                      eproj + (size_t)l * NEDGES * HIDDIM);
        cudaEventRecord(evEdge[l], s1);
    }

    // ---- main chain on default stream ----
    const __half* xcur = x16;
    for (int l = 0; l < NLAYER; l++) {
        __half* xn = (l & 1) ? b16B : b16A;
        dim3 gN((NNODES + 127) / 128, 4);
        gemm_node<<<gN, 256>>>(xcur, wlt + (size_t)l * 256 * 256, wrt + (size_t)l * 256 * 256,
                               bl + l * 256, br + l * 256, xl, xr, NNODES);
        cudaStreamWaitEvent(0, evEdge[l], 0);
        fused_gat_kernel<<<(NNODES * 32 + 255) / 256, 256>>>(
            att + l * 256, bias + l * 256, eloop + l * 256,
            eproj + (size_t)l * NEDGES * HIDDIM, xn);
        xcur = xn;
    }

    // join side stream before final (not strictly needed, but keeps graph tidy)
    cudaEventRecord(evJoin, s1);
    cudaStreamWaitEvent(0, evJoin, 0);

    poolmlp_kernel<<<GDIM, 256>>>(xcur, Wp1, bp1, Wp2, bp2, out);
}

// round 17
// speedup vs baseline: 1.1508x; 1.0348x over previous
#include <cuda_runtime.h>
#include <cuda_fp16.h>
#include <cuda_bf16.h>
#include <cstdint>

#define NNODES 100000
#define NEDGES 300000
#define GDIM   2048
#define HIDDIM 256
#define EDIM   64
#define NLAYER 3
#define NBLK   ((NNODES + 255) / 256)   // 391

// ---------------- static device scratch ----------------
__device__ __half g_x16[(size_t)NNODES * HIDDIM];
__device__ __half g_buf16A[(size_t)NNODES * HIDDIM];
__device__ __half g_buf16B[(size_t)NNODES * HIDDIM];
__device__ __half g_xl[(size_t)NNODES * HIDDIM];
__device__ __half g_xr[(size_t)NNODES * HIDDIM];
__device__ __half g_eproj[NLAYER][(size_t)NEDGES * HIDDIM];  // per-layer, CSR order
__device__ __half g_ea16[(size_t)NEDGES * EDIM];
__device__ __half g_wlt[(size_t)NLAYER * HIDDIM * HIDDIM];
__device__ __half g_wrt[(size_t)NLAYER * HIDDIM * HIDDIM];
__device__ __half g_wet[(size_t)NLAYER * HIDDIM * EDIM];
__device__ float g_eloop[NLAYER * HIDDIM];
__device__ float g_esum[EDIM];
// CSR (dst-sorted edges)
__device__ int g_cnt[NNODES];
__device__ int g_bsum[512];
__device__ int g_rowptr[NNODES + 1];
__device__ int g_woff[NNODES];
__device__ int g_ssrc[NEDGES];
__device__ int g_seid[NEDGES];
__device__ int g_gstart[GDIM + 1];

// ---------------- helpers ----------------
__device__ __forceinline__ void mma_f16(float* c, const uint32_t* a, const uint32_t* b) {
    asm volatile("mma.sync.aligned.m16n8k16.row.col.f32.f16.f16.f32 "
                 "{%0,%1,%2,%3}, {%4,%5,%6,%7}, {%8,%9}, {%0,%1,%2,%3};"
                 : "+f"(c[0]), "+f"(c[1]), "+f"(c[2]), "+f"(c[3])
                 : "r"(a[0]), "r"(a[1]), "r"(a[2]), "r"(a[3]), "r"(b[0]), "r"(b[1]));
}
__device__ __forceinline__ void cp16(void* smem, const void* gmem) {
    uint32_t s;
    asm("{ .reg .u64 t; cvta.to.shared.u64 t, %1; cvt.u32.u64 %0, t; }" : "=r"(s) : "l"(smem));
    asm volatile("cp.async.cg.shared.global [%0], [%1], 16;" :: "r"(s), "l"(gmem));
}
__device__ __forceinline__ int swz(int row, int col) {
    return ((((col >> 3) ^ ((row >> 1) & 3)) << 3) | (col & 7));
}
__device__ __forceinline__ uint4 pack8h(float4 a, float4 b) {
    uint4 u;
    *(__half2*)&u.x = __floats2half2_rn(a.x, a.y);
    *(__half2*)&u.y = __floats2half2_rn(a.z, a.w);
    *(__half2*)&u.z = __floats2half2_rn(b.x, b.y);
    *(__half2*)&u.w = __floats2half2_rn(b.z, b.w);
    return u;
}
__device__ __forceinline__ void fp16x8_expand(uint4 u, float4& o0, float4& o1) {
    float2 f0 = __half22float2(*(__half2*)&u.x);
    float2 f1 = __half22float2(*(__half2*)&u.y);
    float2 f2 = __half22float2(*(__half2*)&u.z);
    float2 f3 = __half22float2(*(__half2*)&u.w);
    o0 = make_float4(f0.x, f0.y, f1.x, f1.y);
    o1 = make_float4(f2.x, f2.y, f3.x, f3.y);
}
__device__ __forceinline__ void st_stream_b32(void* p, uint32_t v) {
    asm volatile("st.global.cs.b32 [%0], %1;" :: "l"(p), "r"(v) : "memory");
}
__device__ __forceinline__ uint4 ld_stream_v4(const void* p) {
    uint4 u;
    asm volatile("ld.global.cs.v4.u32 {%0,%1,%2,%3}, [%4];"
                 : "=r"(u.x), "=r"(u.y), "=r"(u.z), "=r"(u.w) : "l"(p));
    return u;
}

// ========== fp16 GEMM: cp.async 2-stage, BK=32, CTA 128x128, 8 warps 4x2 ==========
#define GEMM_LOAD16(s, k0, Ap, Bp, K, M, row0, col0)                                  \
    _Pragma("unroll") for (int i = 0; i < 2; i++) {                                   \
        int idx = tid + i * 256;                                                      \
        int r = idx >> 2, q = (idx & 3) * 8;                                          \
        int ar = (row0) + r; if (ar >= (M)) ar = (M) - 1;                             \
        cp16(&As[s][r][swz(r, q)], (Ap) + (size_t)ar * (K) + (k0) + q);               \
        cp16(&Bs[s][r][swz(r, q)], (Bp) + (size_t)((col0) + r) * (K) + (k0) + q);     \
    }                                                                                 \
    asm volatile("cp.async.commit_group;" ::: "memory");

#define GEMM_BODY16(Ap, Bp, K, M, row0, col0)                                          \
    float acc[2][8][4];                                                               \
    _Pragma("unroll") for (int mt = 0; mt < 2; mt++)                                  \
    _Pragma("unroll") for (int nt = 0; nt < 8; nt++)                                  \
    _Pragma("unroll") for (int i = 0; i < 4; i++) acc[mt][nt][i] = 0.0f;              \
    GEMM_LOAD16(0, 0, Ap, Bp, K, M, row0, col0)                                       \
    const int NKC = (K) / 32;                                                         \
    for (int kc = 0; kc < NKC; kc++) {                                                \
        if (kc + 1 < NKC) {                                                           \
            GEMM_LOAD16((kc + 1) & 1, (kc + 1) * 32, Ap, Bp, K, M, row0, col0)        \
            asm volatile("cp.async.wait_group 1;" ::: "memory");                      \
        } else {                                                                      \
            asm volatile("cp.async.wait_group 0;" ::: "memory");                      \
        }                                                                             \
        __syncthreads();                                                              \
        const int st = kc & 1;                                                        \
        _Pragma("unroll") for (int ks = 0; ks < 2; ks++) {                            \
            const int kb = ks * 16;                                                   \
            uint32_t bf[8][2];                                                        \
            _Pragma("unroll") for (int nt = 0; nt < 8; nt++) {                        \
                const int bn = warp_n * 64 + nt * 8 + lq;                             \
                bf[nt][0] = *(const uint32_t*)&Bs[st][bn][swz(bn, kb + lr * 2)];      \
                bf[nt][1] = *(const uint32_t*)&Bs[st][bn][swz(bn, kb + lr * 2 + 8)];  \
            }                                                                         \
            _Pragma("unroll") for (int mt = 0; mt < 2; mt++) {                        \
                const int ar = warp_m * 32 + mt * 16 + lq;                            \
                uint32_t af[4];                                                       \
                af[0] = *(const uint32_t*)&As[st][ar][swz(ar, kb + lr * 2)];          \
                af[1] = *(const uint32_t*)&As[st][ar + 8][swz(ar + 8, kb + lr * 2)];  \
                af[2] = *(const uint32_t*)&As[st][ar][swz(ar, kb + lr * 2 + 8)];      \
                af[3] = *(const uint32_t*)&As[st][ar + 8][swz(ar + 8, kb + lr * 2 + 8)]; \
                _Pragma("unroll") for (int nt = 0; nt < 8; nt++)                      \
                    mma_f16(acc[mt][nt], af, bf[nt]);                                 \
            }                                                                         \
        }                                                                             \
        __syncthreads();                                                              \
    }

// ---------------- fused node GEMM ----------------
__global__ __launch_bounds__(256)
void gemm_node(const __half* __restrict__ A,
               const __half* __restrict__ Wlt, const __half* __restrict__ Wrt,
               const float* __restrict__ bl_, const float* __restrict__ br_,
               __half* __restrict__ Cl, __half* __restrict__ Cr, int M) {
    __shared__ __align__(16) __half As[2][128][32];
    __shared__ __align__(16) __half Bs[2][128][32];
    const int tid = threadIdx.x, warp = tid >> 5, lane = tid & 31;
    const int warp_m = warp & 3, warp_n = warp >> 2;
    const int row0 = blockIdx.x * 128;
    const int col0 = (blockIdx.y & 1) * 128;
    const __half* W   = (blockIdx.y < 2) ? Wlt : Wrt;
    const float* bias = (blockIdx.y < 2) ? bl_ : br_;
    __half* C         = (blockIdx.y < 2) ? Cl  : Cr;
    const int lq = lane >> 2, lr = lane & 3;

    GEMM_BODY16(A, W, 256, M, row0, col0)

    const int r_base = row0 + warp_m * 32 + lq;
    const int c_base = col0 + warp_n * 64 + lr * 2;
#pragma unroll
    for (int nt = 0; nt < 8; nt++) {
        int c = c_base + nt * 8;
        float2 bv = *(const float2*)(bias + c);
#pragma unroll
        for (int mt = 0; mt < 2; mt++) {
            int r = r_base + mt * 16;
            if (r < M) {
                __half2 v = __floats2half2_rn(acc[mt][nt][0] + bv.x, acc[mt][nt][1] + bv.y);
                *(__half2*)(C + (size_t)r * 256 + c) = v;
            }
            if (r + 8 < M) {
                __half2 v = __floats2half2_rn(acc[mt][nt][2] + bv.x, acc[mt][nt][3] + bv.y);
                *(__half2*)(C + (size_t)(r + 8) * 256 + c) = v;
            }
        }
    }
}

// ---------------- edge GEMM: eproj (per-layer buffer) stored with .cs ----------------
__global__ __launch_bounds__(256)
void gemm_edge(const __half* __restrict__ Wet, __half* __restrict__ eout) {
    __shared__ __align__(16) __half As[2][128][32];
    __shared__ __align__(16) __half Bs[2][128][32];
    const __half* A = g_ea16;
    const int tid = threadIdx.x, warp = tid >> 5, lane = tid & 31;
    const int warp_m = warp & 3, warp_n = warp >> 2;
    const int row0 = blockIdx.x * 128;
    const int col0 = blockIdx.y * 128;
    const int lq = lane >> 2, lr = lane & 3;
    const int M = NEDGES;

    GEMM_BODY16(A, Wet, 64, M, row0, col0)

    const int r_base = row0 + warp_m * 32 + lq;
    const int c_base = col0 + warp_n * 64 + lr * 2;
#pragma unroll
    for (int nt = 0; nt < 8; nt++) {
        int c = c_base + nt * 8;
#pragma unroll
        for (int mt = 0; mt < 2; mt++) {
            int r = r_base + mt * 16;
            if (r < M) {
                __half2 v = __floats2half2_rn(acc[mt][nt][0], acc[mt][nt][1]);
                st_stream_b32(eout + (size_t)r * 256 + c, *(uint32_t*)&v);
            }
            if (r + 8 < M) {
                __half2 v = __floats2half2_rn(acc[mt][nt][2], acc[mt][nt][3]);
                st_stream_b32(eout + (size_t)(r + 8) * 256 + c, *(uint32_t*)&v);
            }
        }
    }
}

// ---------------- conversion kernels ----------------
__global__ void convx_kernel(const float* __restrict__ x) {
    int i = blockIdx.x * blockDim.x + threadIdx.x;
    if (i >= NNODES * 32) return;
    const float4* s = (const float4*)x + (size_t)i * 2;
    ((uint4*)g_x16)[i] = pack8h(s[0], s[1]);
}
__global__ void convw_kernel(const float* __restrict__ W, __half* __restrict__ Wt, int K) {
    __shared__ float t[32][33];
    int l = blockIdx.z;
    const float* Wl = W + (size_t)l * K * 256;
    __half* Wtl = Wt + (size_t)l * K * 256;
    int n0 = blockIdx.x * 32, k0 = blockIdx.y * 32;
    int tx = threadIdx.x, ty = threadIdx.y;
#pragma unroll
    for (int j = 0; j < 32; j += 8) t[ty + j][tx] = Wl[(size_t)(k0 + ty + j) * 256 + n0 + tx];
    __syncthreads();
#pragma unroll
    for (int j = 0; j < 32; j += 8)
        Wtl[(size_t)(n0 + ty + j) * K + k0 + tx] = __float2half(t[tx][ty + j]);
}

// ---------------- CSR build ----------------
__global__ void hist_kernel(const int* __restrict__ dst) {
    int e = blockIdx.x * blockDim.x + threadIdx.x;
    if (e < NEDGES) atomicAdd(&g_cnt[dst[e]], 1);
}
__global__ void blocksum_kernel() {
    int i = blockIdx.x * 256 + threadIdx.x;
    int v = (i < NNODES) ? g_cnt[i] : 0;
    __shared__ int ws[8];
#pragma unroll
    for (int o = 16; o; o >>= 1) v += __shfl_down_sync(0xffffffffu, v, o);
    if ((threadIdx.x & 31) == 0) ws[threadIdx.x >> 5] = v;
    __syncthreads();
    if (threadIdx.x == 0) {
        int s = 0;
#pragma unroll
        for (int j = 0; j < 8; j++) s += ws[j];
        g_bsum[blockIdx.x] = s;
    }
}
__global__ void scanb_kernel() {
    __shared__ int sm[512];
    int i = threadIdx.x;
    int v = (i < NBLK) ? g_bsum[i] : 0;
    sm[i] = v;
    __syncthreads();
    for (int s = 1; s < 512; s <<= 1) {
        int t = (i >= s) ? sm[i - s] : 0;
        __syncthreads();
        sm[i] += t;
        __syncthreads();
    }
    if (i < NBLK) g_bsum[i] = sm[i] - v;
}
__global__ void rowptr_kernel() {
    int tid = threadIdx.x;
    int i = blockIdx.x * 256 + tid;
    int v = (i < NNODES) ? g_cnt[i] : 0;
    __shared__ int sm[256];
    sm[tid] = v;
    __syncthreads();
    for (int s = 1; s < 256; s <<= 1) {
        int t = (tid >= s) ? sm[tid - s] : 0;
        __syncthreads();
        sm[tid] += t;
        __syncthreads();
    }
    int ex = sm[tid] - v + g_bsum[blockIdx.x];
    if (i < NNODES) { g_rowptr[i] = ex; g_woff[i] = ex; }
    if (i == NNODES - 1) g_rowptr[NNODES] = NEDGES;
}
__global__ void fill_kernel(const int* __restrict__ src, const int* __restrict__ dst) {
    int e = blockIdx.x * blockDim.x + threadIdx.x;
    if (e >= NEDGES) return;
    int d = dst[e];
    int pos = atomicAdd(&g_woff[d], 1);
    g_ssrc[pos] = src[e];
    g_seid[pos] = e;
}
__global__ void permute_ea_kernel(const float* __restrict__ ea) {
    int gt = blockIdx.x * blockDim.x + threadIdx.x;
    if (gt >= NEDGES * 8) return;
    int i = gt >> 3, q = gt & 7;
    int e = g_seid[i];
    const float4* s = (const float4*)(ea + (size_t)e * 64 + q * 8);
    ((uint4*)g_ea16)[(size_t)i * 8 + q] = pack8h(s[0], s[1]);
}
__global__ void gbounds_kernel(const int* __restrict__ batch) {
    int g = blockIdx.x * blockDim.x + threadIdx.x;
    if (g > GDIM) return;
    int lo = 0, hi = NNODES;
    while (lo < hi) {
        int mid = (lo + hi) >> 1;
        if (batch[mid] < g) lo = mid + 1; else hi = mid;
    }
    g_gstart[g] = lo;
}

// ---------------- edge_attr column sums + eloop ----------------
__global__ void esum_kernel(const float* __restrict__ ea) {
    int col = threadIdx.x & 63;
    int rowsPerBlk = blockDim.x >> 6;
    int r0 = blockIdx.x * rowsPerBlk + (threadIdx.x >> 6);
    int rstride = gridDim.x * rowsPerBlk;
    float s = 0.0f;
    for (int r = r0; r < NEDGES; r += rstride) s += ea[(size_t)r * EDIM + col];
    atomicAdd(&g_esum[col], s);
}
__global__ void eloop_kernel(const float* __restrict__ We) {
    int l = blockIdx.x;
    int j = threadIdx.x;
    const float* W = We + (size_t)l * EDIM * 256;
    const float inv = 1.0f / (float)NEDGES;
    float acc = 0.0f;
#pragma unroll
    for (int k = 0; k < EDIM; k++) acc = fmaf(g_esum[k] * inv, W[k * 256 + j], acc);
    g_eloop[l * 256 + j] = acc;
}

// ---------------- fused GAT edge phase ----------------
__global__ __launch_bounds__(256)
void fused_gat_kernel(const float* __restrict__ att, const float* __restrict__ bias,
                      const float* __restrict__ eloop, const __half* __restrict__ eproj,
                      __half* __restrict__ xn) {
    int gt = blockIdx.x * blockDim.x + threadIdx.x;
    int d = gt >> 5, lane = gt & 31;
    if (d >= NNODES) return;
    const int off = lane * 8;

    float4 xr0, xr1;
    fp16x8_expand(*(const uint4*)(g_xr + (size_t)d * 256 + off), xr0, xr1);
    float4 at0 = *(const float4*)(att + off);
    float4 at1 = *(const float4*)(att + off + 4);

    float acc[8];
    float denom;
    {
        float4 a0, a1;
        fp16x8_expand(*(const uint4*)(g_xl + (size_t)d * 256 + off), a0, a1);
        float4 e0 = *(const float4*)(eloop + off);
        float4 e1 = *(const float4*)(eloop + off + 4);
        float t = 0.0f, m;
        m = a0.x + xr0.x + e0.x; m = fmaxf(m, 0.2f * m); t = fmaf(m, at0.x, t);
        m = a0.y + xr0.y + e0.y; m = fmaxf(m, 0.2f * m); t = fmaf(m, at0.y, t);
        m = a0.z + xr0.z + e0.z; m = fmaxf(m, 0.2f * m); t = fmaf(m, at0.z, t);
        m = a0.w + xr0.w + e0.w; m = fmaxf(m, 0.2f * m); t = fmaf(m, at0.w, t);
        m = a1.x + xr1.x + e1.x; m = fmaxf(m, 0.2f * m); t = fmaf(m, at1.x, t);
        m = a1.y + xr1.y + e1.y; m = fmaxf(m, 0.2f * m); t = fmaf(m, at1.y, t);
        m = a1.z + xr1.z + e1.z; m = fmaxf(m, 0.2f * m); t = fmaf(m, at1.z, t);
        m = a1.w + xr1.w + e1.w; m = fmaxf(m, 0.2f * m); t = fmaf(m, at1.w, t);
        t += __shfl_down_sync(0xffffffffu, t, 4, 8);
        t += __shfl_down_sync(0xffffffffu, t, 2, 8);
        t += __shfl_down_sync(0xffffffffu, t, 1, 8);
        float p = __expf(__shfl_sync(0xffffffffu, t, 0, 8));
        denom = p;
        acc[0] = p * a0.x; acc[1] = p * a0.y; acc[2] = p * a0.z; acc[3] = p * a0.w;
        acc[4] = p * a1.x; acc[5] = p * a1.y; acc[6] = p * a1.z; acc[7] = p * a1.w;
    }
    const int beg = g_rowptr[d], end = g_rowptr[d + 1];
    uint4 au, eu;
    if (beg < end) {
        int s = g_ssrc[beg];
        au = *(const uint4*)(g_xl + (size_t)s * 256 + off);
        eu = ld_stream_v4(eproj + (size_t)beg * 256 + off);
    }
    for (int i = beg; i < end; i++) {
        uint4 a_cur = au, e_cur = eu;
        if (i + 1 < end) {
            int s = g_ssrc[i + 1];
            au = *(const uint4*)(g_xl + (size_t)s * 256 + off);
            eu = ld_stream_v4(eproj + (size_t)(i + 1) * 256 + off);
        }
        float4 a0, a1, e0, e1;
        fp16x8_expand(a_cur, a0, a1);
        fp16x8_expand(e_cur, e0, e1);
        float t = 0.0f, m;
        m = a0.x + xr0.x + e0.x; m = fmaxf(m, 0.2f * m); t = fmaf(m, at0.x, t);
        m = a0.y + xr0.y + e0.y; m = fmaxf(m, 0.2f * m); t = fmaf(m, at0.y, t);
        m = a0.z + xr0.z + e0.z; m = fmaxf(m, 0.2f * m); t = fmaf(m, at0.z, t);
        m = a0.w + xr0.w + e0.w; m = fmaxf(m, 0.2f * m); t = fmaf(m, at0.w, t);
        m = a1.x + xr1.x + e1.x; m = fmaxf(m, 0.2f * m); t = fmaf(m, at1.x, t);
        m = a1.y + xr1.y + e1.y; m = fmaxf(m, 0.2f * m); t = fmaf(m, at1.y, t);
        m = a1.z + xr1.z + e1.z; m = fmaxf(m, 0.2f * m); t = fmaf(m, at1.z, t);
        m = a1.w + xr1.w + e1.w; m = fmaxf(m, 0.2f * m); t = fmaf(m, at1.w, t);
        t += __shfl_down_sync(0xffffffffu, t, 4, 8);
        t += __shfl_down_sync(0xffffffffu, t, 2, 8);
        t += __shfl_down_sync(0xffffffffu, t, 1, 8);
        float p = __expf(__shfl_sync(0xffffffffu, t, 0, 8));
        denom += p;
        acc[0] = fmaf(p, a0.x, acc[0]); acc[1] = fmaf(p, a0.y, acc[1]);
        acc[2] = fmaf(p, a0.z, acc[2]); acc[3] = fmaf(p, a0.w, acc[3]);
        acc[4] = fmaf(p, a1.x, acc[4]); acc[5] = fmaf(p, a1.y, acc[5]);
        acc[6] = fmaf(p, a1.z, acc[6]); acc[7] = fmaf(p, a1.w, acc[7]);
    }
    float inv = 1.0f / (denom + 1e-16f);
    float4 b0 = *(const float4*)(bias + off);
    float4 b1 = *(const float4*)(bias + off + 4);
    float4 o0, o1;
    o0.x = fmaxf(fmaf(acc[0], inv, b0.x), 0.f); o0.y = fmaxf(fmaf(acc[1], inv, b0.y), 0.f);
    o0.z = fmaxf(fmaf(acc[2], inv, b0.z), 0.f); o0.w = fmaxf(fmaf(acc[3], inv, b0.w), 0.f);
    o1.x = fmaxf(fmaf(acc[4], inv, b1.x), 0.f); o1.y = fmaxf(fmaf(acc[5], inv, b1.y), 0.f);
    o1.z = fmaxf(fmaf(acc[6], inv, b1.z), 0.f); o1.w = fmaxf(fmaf(acc[7], inv, b1.w), 0.f);
    *(uint4*)(xn + (size_t)d * 256 + off) = pack8h(o0, o1);
}

// ---------------- fused pool + MLP ----------------
__global__ __launch_bounds__(256)
void poolmlp_kernel(const __half* __restrict__ xf,
                    const float* __restrict__ Wp1, const float* __restrict__ bp1,
                    const float* __restrict__ Wp2, const float* __restrict__ bp2,
                    float* __restrict__ out) {
    int g = blockIdx.x;
    int beg = g_gstart[g], end = g_gstart[g + 1];
    int tid = threadIdx.x;
    __shared__ float pooled[256];
    __shared__ float hsm[256];
    __shared__ float partial[4];

    float s = 0.0f;
    for (int n = beg; n < end; n++)
        s += __half2float(xf[(size_t)n * 256 + tid]);
    float cnt = fmaxf((float)(end - beg), 1.0f);
    pooled[tid] = s / cnt;
    __syncthreads();

    int j = tid & 127, half = tid >> 7;
    float acc = 0.0f;
    const float* w = Wp1 + (size_t)(half * 128) * 128 + j;
#pragma unroll 8
    for (int k = 0; k < 128; k++) acc = fmaf(pooled[half * 128 + k], w[k * 128], acc);
    hsm[tid] = acc;
    __syncthreads();
    if (tid < 128) {
        float h = fmaxf(hsm[tid] + hsm[tid + 128] + bp1[tid], 0.0f) * Wp2[tid];
#pragma unroll
        for (int o = 16; o; o >>= 1) h += __shfl_down_sync(0xffffffffu, h, o);
        if ((tid & 31) == 0) partial[tid >> 5] = h;
    }
    __syncthreads();
    if (tid == 0)
        out[g] = partial[0] + partial[1] + partial[2] + partial[3] + bp2[0];
}

// ---------------- launcher (two-sided fork/join multi-stream capture) ----------------
extern "C" void kernel_launch(void* const* d_in, const int* in_sizes, int n_in,
                              void* d_out, int out_size) {
    const float* x     = (const float*)d_in[0];
    const int*   ei    = (const int*)  d_in[1];
    const float* ea    = (const float*)d_in[2];
    const int*   batch = (const int*)  d_in[3];
    const float* Wl    = (const float*)d_in[4];
    const float* bl    = (const float*)d_in[5];
    const float* Wr    = (const float*)d_in[6];
    const float* br    = (const float*)d_in[7];
    const float* We    = (const float*)d_in[8];
    const float* att   = (const float*)d_in[9];
    const float* bias  = (const float*)d_in[10];
    const float* Wp1   = (const float*)d_in[11];
    const float* bp1   = (const float*)d_in[12];
    const float* Wp2   = (const float*)d_in[13];
    const float* bp2   = (const float*)d_in[14];
    float* out = (float*)d_out;
    const int* src = ei;
    const int* dst = ei + NEDGES;

    float *esum, *eloop;
    __half *x16, *b16A, *b16B, *xl, *xr, *wlt, *wrt, *wet, *eproj;
    int* cnt;
    cudaGetSymbolAddress((void**)&x16,  g_x16);
    cudaGetSymbolAddress((void**)&b16A, g_buf16A);
    cudaGetSymbolAddress((void**)&b16B, g_buf16B);
    cudaGetSymbolAddress((void**)&xl,   g_xl);
    cudaGetSymbolAddress((void**)&xr,   g_xr);
    cudaGetSymbolAddress((void**)&wlt,  g_wlt);
    cudaGetSymbolAddress((void**)&wrt,  g_wrt);
    cudaGetSymbolAddress((void**)&wet,  g_wet);
    cudaGetSymbolAddress((void**)&eproj, g_eproj);
    cudaGetSymbolAddress((void**)&esum, g_esum);
    cudaGetSymbolAddress((void**)&eloop, g_eloop);
    cudaGetSymbolAddress((void**)&cnt,  g_cnt);

    // persistent side stream + events
    static cudaStream_t s1 = nullptr;
    static cudaEvent_t evStart = nullptr, evConv = nullptr, evCSR = nullptr;
    static cudaEvent_t evEdge[NLAYER] = {nullptr, nullptr, nullptr};
    static cudaEvent_t evJoin = nullptr;
    if (!s1) {
        cudaStreamCreateWithFlags(&s1, cudaStreamNonBlocking);
        cudaEventCreateWithFlags(&evStart, cudaEventDisableTiming);
        cudaEventCreateWithFlags(&evConv, cudaEventDisableTiming);
        cudaEventCreateWithFlags(&evCSR, cudaEventDisableTiming);
        for (int l = 0; l < NLAYER; l++) cudaEventCreateWithFlags(&evEdge[l], cudaEventDisableTiming);
        cudaEventCreateWithFlags(&evJoin, cudaEventDisableTiming);
    }

    // ---- fork point ----
    cudaMemsetAsync(cnt, 0, NNODES * sizeof(int));   // first op on capture stream
    cudaEventRecord(evStart, 0);
    cudaStreamWaitEvent(s1, evStart, 0);

    // ---- s1: conversions (independent of CSR) ----
    convx_kernel<<<(NNODES * 32 + 255) / 256, 256, 0, s1>>>(x);
    dim3 tb(32, 8);
    convw_kernel<<<dim3(8, 8, 3), tb, 0, s1>>>(Wl, wlt, 256);
    convw_kernel<<<dim3(8, 8, 3), tb, 0, s1>>>(Wr, wrt, 256);
    convw_kernel<<<dim3(8, 2, 3), tb, 0, s1>>>(We, wet, 64);
    cudaMemsetAsync(esum, 0, EDIM * sizeof(float), s1);
    esum_kernel<<<512, 256, 0, s1>>>(ea);
    eloop_kernel<<<NLAYER, 256, 0, s1>>>(We);
    cudaEventRecord(evConv, s1);

    // ---- s0: CSR build chain ----
    hist_kernel<<<(NEDGES + 255) / 256, 256>>>(dst);
    blocksum_kernel<<<NBLK, 256>>>();
    scanb_kernel<<<1, 512>>>();
    rowptr_kernel<<<NBLK, 256>>>();
    fill_kernel<<<(NEDGES + 255) / 256, 256>>>(src, dst);
    permute_ea_kernel<<<(NEDGES * 8 + 255) / 256, 256>>>(ea);
    gbounds_kernel<<<(GDIM + 256) / 256, 256>>>(batch);
    cudaEventRecord(evCSR, 0);

    // ---- s1: edge GEMMs (need permute_ea from s0 + wet from s1) ----
    cudaStreamWaitEvent(s1, evCSR, 0);
    dim3 gE((NEDGES + 127) / 128, 2);
    for (int l = 0; l < NLAYER; l++) {
        gemm_edge<<<gE, 256, 0, s1>>>(wet + (size_t)l * 64 * 256,
                                      eproj + (size_t)l * NEDGES * HIDDIM);
        cudaEventRecord(evEdge[l], s1);
    }

    // ---- s0: main chain (needs conversions) ----
    cudaStreamWaitEvent(0, evConv, 0);
    const __half* xcur = x16;
    for (int l = 0; l < NLAYER; l++) {
        __half* xn = (l & 1) ? b16B : b16A;
        dim3 gN((NNODES + 127) / 128, 4);
        gemm_node<<<gN, 256>>>(xcur, wlt + (size_t)l * 256 * 256, wrt + (size_t)l * 256 * 256,
                               bl + l * 256, br + l * 256, xl, xr, NNODES);
        cudaStreamWaitEvent(0, evEdge[l], 0);
        fused_gat_kernel<<<(NNODES * 32 + 255) / 256, 256>>>(
            att + l * 256, bias + l * 256, eloop + l * 256,
            eproj + (size_t)l * NEDGES * HIDDIM, xn);
        xcur = xn;
    }

    // join side stream
    cudaEventRecord(evJoin, s1);
    cudaStreamWaitEvent(0, evJoin, 0);

    poolmlp_kernel<<<GDIM, 256>>>(xcur, Wp1, bp1, Wp2, bp2, out);
}